// round 14
// baseline (speedup 1.0000x reference)
#include <cuda_runtime.h>
#include <cuda_fp16.h>
#include <cstdint>

#define D 128
#define NA 100000
#define NB 150000
#define NG 2000
#define NTOT (NA + NB + NG)      // 252000
#define DEG_TOT 756000
#define NE_TOT 1352000
#define NTILES 5910
#define BN_EPS 1e-5f
#define SCAN_NB ((DEG_TOT + 1023) / 1024)   // 739

#define EBLK ((NE_TOT + 255) / 256)          // 5282
#define CBLK ((NTOT * 32 + 255) / 256)       // 31500

// ---------------- constant boundary tables ----------------
__constant__ int c_doff[10] = {0,150000,250000,252000,352000,354000,504000,604000,754000,756000};
__constant__ int c_soff[10] = {0,100000,250000,350000,352000,502000,504000,604000,754000,756000};
__constant__ int c_eoff[10] = {0,300000,600000,700000,800000,950000,1100000,1200000,1350000,1352000};
__constant__ int c_tbase[10] = {0,1172,1954,1970,2752,2768,3940,4722,5894,5910};
__constant__ int c_stoff[9] = {0, NA, 0, NA + NB, NA, NA + NB, 0, NA, NA + NB};
__constant__ int c_ndst[9] = {NB, NA, NG, NA, NG, NB, NA, NB, NG};
__constant__ int c_rl[9] = {1, 3, 6, 0, 5, 7, 2, 4, 8};
__constant__ int c_toff[3] = {0, NA, NA + NB};

// ---------------- device scratch ----------------
__device__ int g_odeg[DEG_TOT];
__device__ int g_ideg[DEG_TOT];
__device__ int g_offs[DEG_TOT];
__device__ int2 g_rowinfo[DEG_TOT];               // {csr_off (fill), deg (scan1)}
__device__ int g_cursor[DEG_TOT];
__device__ int g_bsum[SCAN_NB];
__device__ int2 g_epack[NE_TOT];                  // {src_byte_off, ns fp32 bits}
__device__ float g_ns[DEG_TOT];
__device__ float g_nd[DEG_TOT];
__device__ __align__(128) __half g_fh[(size_t)NTOT * D];
__device__ __align__(128) __half g_gout[(size_t)DEG_TOT * D];
__device__ float g_stats[9 * 2 * D];
__device__ float g_scale[9 * D];
__device__ float g_shift[9 * D];
__device__ __align__(128) __half g_wh[18 * D * D];

struct EdgePtrs { const int* s[9]; const int* d[9]; };

// ---------------- helpers ----------------
__device__ __forceinline__ uint32_t sw128(uint32_t o) { return o ^ ((o >> 3) & 0x70); }
__device__ __forceinline__ uint32_t toff128(uint32_t row, uint32_t k) {
    return ((k >> 6) << 14) + sw128(row * 128 + ((k & 63) << 1));
}
__device__ __forceinline__ uint32_t smem_u32(const void* p) {
    uint32_t a;
    asm("{ .reg .u64 t; cvta.to.shared.u64 t, %1; cvt.u32.u64 %0, t; }" : "=r"(a) : "l"(p));
    return a;
}
__device__ __forceinline__ void ldsm4(uint32_t& r0, uint32_t& r1, uint32_t& r2, uint32_t& r3,
                                      uint32_t addr) {
    asm volatile("ldmatrix.sync.aligned.m8n8.x4.shared.b16 {%0,%1,%2,%3}, [%4];"
                 : "=r"(r0), "=r"(r1), "=r"(r2), "=r"(r3) : "r"(addr));
}
__device__ __forceinline__ void mma_f16(float* d, const uint32_t* a, uint32_t b0, uint32_t b1) {
    asm volatile(
        "mma.sync.aligned.m16n8k16.row.col.f32.f16.f16.f32 "
        "{%0,%1,%2,%3}, {%4,%5,%6,%7}, {%8,%9}, {%0,%1,%2,%3};"
        : "+f"(d[0]), "+f"(d[1]), "+f"(d[2]), "+f"(d[3])
        : "r"(a[0]), "r"(a[1]), "r"(a[2]), "r"(a[3]), "r"(b0), "r"(b1));
}
__device__ __forceinline__ void cpasync16(uint32_t dst, const void* src) {
    asm volatile("cp.async.ca.shared.global [%0], [%1], 16;" :: "r"(dst), "l"(src));
}
__device__ __forceinline__ void acc8(float* acc, const uint4& v, float w) {
    float2 t0 = __half22float2(*(__half2*)&v.x);
    float2 t1 = __half22float2(*(__half2*)&v.y);
    float2 t2 = __half22float2(*(__half2*)&v.z);
    float2 t3 = __half22float2(*(__half2*)&v.w);
    acc[0] += t0.x * w; acc[1] += t0.y * w;
    acc[2] += t1.x * w; acc[3] += t1.y * w;
    acc[4] += t2.x * w; acc[5] += t2.y * w;
    acc[6] += t3.x * w; acc[7] += t3.y * w;
}

// ---------------- launch 0: W->fp16 swizzled + degree count + feat->fp16 -------
__global__ void k_prep(EdgePtrs E, const float* __restrict__ W,
                       const float4* __restrict__ fa4, const float4* __restrict__ fb4,
                       const float4* __restrict__ fg4) {
    if (blockIdx.x < 18) {
        int rel = blockIdx.x;
        const float* w = W + (size_t)rel * D * D;
        char* wh = (char*)g_wh + (size_t)rel * D * D * 2;
        for (int idx = threadIdx.x; idx < D * D; idx += blockDim.x) {
            int k = idx >> 7, n = idx & 127;
            *(__half*)(wh + toff128(n, k)) = __float2half_rn(w[idx]);
        }
        return;
    }
    if (blockIdx.x < 18 + EBLK) {
        int e = (blockIdx.x - 18) * blockDim.x + threadIdx.x;
        if (e >= NE_TOT) return;
        int rel = 0;
#pragma unroll
        for (int r = 1; r < 9; r++) if (e >= c_eoff[r]) rel = r;
        int le = e - c_eoff[rel];
        atomicAdd(&g_odeg[c_soff[rel] + E.s[rel][le]], 1);
        atomicAdd(&g_ideg[c_doff[rel] + E.d[rel][le]], 1);
        return;
    }
    int i = (blockIdx.x - 18 - EBLK) * blockDim.x + threadIdx.x;
    if (i >= NTOT * 32) return;
    int t = (i < NA * 32) ? 0 : (i < (NA + NB) * 32) ? 1 : 2;
    const float4* src = (t == 0) ? fa4 : (t == 1) ? fb4 : fg4;
    int base4 = (t == 0) ? 0 : (t == 1) ? NA * 32 : (NA + NB) * 32;
    float4 v = src[i - base4];
    ((__half2*)g_fh)[i * 2] = __floats2half2_rn(v.x, v.y);
    ((__half2*)g_fh)[i * 2 + 1] = __floats2half2_rn(v.z, v.w);
}

// ---------------- launch 1: scan + ns/nd + rowinfo.deg + cursor/stats zero -----
__global__ void k_scan1() {
    int tid = threadIdx.x;
    int gid = blockIdx.x * 1024 + tid;
    int lane = tid & 31;
    int w = tid >> 5;
    int v = (gid < DEG_TOT) ? g_ideg[gid] : 0;
    if (gid < DEG_TOT) {
        int od = g_odeg[gid];
        g_ns[gid] = (od > 0) ? rsqrtf((float)od) : 0.f;
        g_nd[gid] = (v > 0) ? rsqrtf((float)v) : 0.f;
        g_cursor[gid] = 0;
        g_rowinfo[gid].y = v;
    }
    if (blockIdx.x == 0) {
        for (int i = tid; i < 9 * 256; i += 1024) g_stats[i] = 0.f;
    }
    int inc = v;
#pragma unroll
    for (int s = 1; s < 32; s <<= 1) {
        int x = __shfl_up_sync(0xffffffffu, inc, s);
        if (lane >= s) inc += x;
    }
    __shared__ int wsum[32];
    if (lane == 31) wsum[w] = inc;
    __syncthreads();
    if (w == 0) {
        int x = (lane < 32) ? wsum[lane] : 0;
        int sc = x;
#pragma unroll
        for (int s = 1; s < 32; s <<= 1) {
            int y = __shfl_up_sync(0xffffffffu, sc, s);
            if (lane >= s) sc += y;
        }
        wsum[lane] = sc - x;
    }
    __syncthreads();
    int excl = inc - v + wsum[w];
    if (gid < DEG_TOT) g_offs[gid] = excl;
    if (tid == 1023) g_bsum[blockIdx.x] = excl + v;
}

// ---------------- launch 2: CSR fill (writes rowinfo.off) ----------------
__global__ __launch_bounds__(256)
void k_fill_all(EdgePtrs E) {
    __shared__ int sb[768];
    __shared__ int wsum[8];
    int t = threadIdx.x;
    int base = t * 3;
    int a0 = (base < SCAN_NB) ? g_bsum[base] : 0;
    int a1 = (base + 1 < SCAN_NB) ? g_bsum[base + 1] : 0;
    int a2 = (base + 2 < SCAN_NB) ? g_bsum[base + 2] : 0;
    int tsum = a0 + a1 + a2;
    int lane = t & 31;
    int inc = tsum;
#pragma unroll
    for (int s = 1; s < 32; s <<= 1) {
        int x = __shfl_up_sync(0xffffffffu, inc, s);
        if (lane >= s) inc += x;
    }
    if (lane == 31) wsum[t >> 5] = inc;
    __syncthreads();
    if (t < 8) {
        int x = wsum[t];
        int sc = x;
#pragma unroll
        for (int s = 1; s < 8; s <<= 1) {
            int y = __shfl_up_sync(0xffu, sc, s);
            if (t >= s) sc += y;
        }
        wsum[t] = sc - x;
    }
    __syncthreads();
    int excl = inc - tsum + wsum[t >> 5];
    sb[base] = excl;
    sb[base + 1] = excl + a0;
    sb[base + 2] = excl + a0 + a1;
    __syncthreads();

    int e = blockIdx.x * blockDim.x + t;
    if (e >= NE_TOT) return;
    int rel = 0;
#pragma unroll
    for (int r = 1; r < 9; r++) if (e >= c_eoff[r]) rel = r;
    int le = e - c_eoff[rel];
    int ss = E.s[rel][le];
    int dd = E.d[rel][le];
    int gslot = c_doff[rel] + dd;
    int ofin = g_offs[gslot] + sb[gslot >> 10];
    int pos = ofin + atomicAdd(&g_cursor[gslot], 1);
    g_epack[pos] = make_int2(ss * 256, __float_as_int(g_ns[c_soff[rel] + ss]));
    g_rowinfo[gslot].x = ofin;
}

// ------- fused gather + GEMM + stats: A tiles live only in smem ----------------
#define OFF_A    0
#define OFF_B    32768
#define OFF_STAT 65536
#define SMEM_DYN (65536 + 1024 + 1024)

__global__ __launch_bounds__(256, 2)
void k_gemm_fused(const __half* __restrict__ fh, const __half* __restrict__ whAll,
                  int layer, __half* __restrict__ out, float* __restrict__ stats) {
    extern __shared__ char smem_raw[];
    char* smem = (char*)((((uintptr_t)smem_raw) + 1023) & ~(uintptr_t)1023);
    uint32_t sa = smem_u32(smem);
    int tid = threadIdx.x;
    int lane = tid & 31;
    int wid = tid >> 5;
    int bid = blockIdx.x;

    int rel = 0;
#pragma unroll
    for (int r = 1; r < 9; r++) if (bid >= c_tbase[r]) rel = r;
    int rowBase = (bid - c_tbase[rel]) * 128;
    int ndst = c_doff[rel + 1] - c_doff[rel];
    int goutBase = c_doff[rel];

    // prefetch B while gathering A
    {
        const char* sB = (const char*)whAll + (size_t)(layer * 9 + rel) * 32768;
#pragma unroll
        for (int i = tid; i < 2048; i += 256) cpasync16(sa + OFF_B + i * 16, sB + i * 16);
        asm volatile("cp.async.commit_group;" ::: "memory");
    }
    ((float*)(smem + OFF_STAT))[tid] = 0.f;

    // ---- gather phase: quarter-warp per row, 4 rows/warp/iter, 4 iters ----
    {
        int l8 = lane & 7;
        const char* fbase = (const char*)fh + (size_t)c_stoff[rel] * 256 + l8 * 32;
        char* atile = smem + OFF_A;
        uint32_t half_tile = (uint32_t)(l8 >> 2) << 14;
        uint32_t colb = (l8 & 3) * 32;
#pragma unroll 1
        for (int it = 0; it < 4; it++) {
            int lrow = it * 32 + wid * 4 + (lane >> 3);
            int grow = rowBase + lrow;
            float acc[16];
#pragma unroll
            for (int j = 0; j < 16; j++) acc[j] = 0.f;
            if (grow < ndst) {
                int gslot = goutBase + grow;
                int2 ri = __ldg(&g_rowinfo[gslot]);
                int dg = ri.y;
                if (dg > 0) {
                    const int2* ep = g_epack + ri.x;
                    int e = 0;
                    for (; e + 2 <= dg; e += 2) {
                        int2 p0 = __ldg(ep + e);
                        int2 p1 = __ldg(ep + e + 1);
                        uint4 v0a = __ldg((const uint4*)(fbase + (uint32_t)p0.x));
                        uint4 v0b = __ldg((const uint4*)(fbase + (uint32_t)p0.x + 16));
                        uint4 v1a = __ldg((const uint4*)(fbase + (uint32_t)p1.x));
                        uint4 v1b = __ldg((const uint4*)(fbase + (uint32_t)p1.x + 16));
                        float w0 = __int_as_float(p0.y), w1 = __int_as_float(p1.y);
                        acc8(acc, v0a, w0);
                        acc8(acc + 8, v0b, w0);
                        acc8(acc, v1a, w1);
                        acc8(acc + 8, v1b, w1);
                    }
                    if (e < dg) {
                        int2 p0 = __ldg(ep + e);
                        uint4 v0a = __ldg((const uint4*)(fbase + (uint32_t)p0.x));
                        uint4 v0b = __ldg((const uint4*)(fbase + (uint32_t)p0.x + 16));
                        float w0 = __int_as_float(p0.y);
                        acc8(acc, v0a, w0);
                        acc8(acc + 8, v0b, w0);
                    }
                    float ndv = __ldg(g_nd + gslot);
#pragma unroll
                    for (int j = 0; j < 16; j++) acc[j] *= ndv;
                }
            }
            uint4 pk0, pk1;
            *(__half2*)&pk0.x = __floats2half2_rn(acc[0], acc[1]);
            *(__half2*)&pk0.y = __floats2half2_rn(acc[2], acc[3]);
            *(__half2*)&pk0.z = __floats2half2_rn(acc[4], acc[5]);
            *(__half2*)&pk0.w = __floats2half2_rn(acc[6], acc[7]);
            *(__half2*)&pk1.x = __floats2half2_rn(acc[8], acc[9]);
            *(__half2*)&pk1.y = __floats2half2_rn(acc[10], acc[11]);
            *(__half2*)&pk1.z = __floats2half2_rn(acc[12], acc[13]);
            *(__half2*)&pk1.w = __floats2half2_rn(acc[14], acc[15]);
            uint32_t rb = (uint32_t)lrow * 128 + colb;
            *(uint4*)(atile + half_tile + sw128(rb)) = pk0;
            *(uint4*)(atile + half_tile + sw128(rb + 16)) = pk1;
        }
    }

    asm volatile("cp.async.wait_group 0;" ::: "memory");
    __syncthreads();

    // ---- GEMM mainloop ----
    float acc[16][4];
#pragma unroll
    for (int t = 0; t < 16; t++)
#pragma unroll
        for (int j = 0; j < 4; j++) acc[t][j] = 0.f;

    int m0 = wid * 16;
    uint32_t rowA = m0 + (lane & 15);
    uint32_t kA = (lane >> 4) << 3;
    uint32_t rowB = (lane & 7) + ((lane >> 4) << 3);
    uint32_t kB = ((lane >> 3) & 1) << 3;

    uint32_t ab = sa + OFF_A;
    uint32_t bb = sa + OFF_B;
#pragma unroll
    for (int k0 = 0; k0 < 128; k0 += 16) {
        uint32_t a[4];
        ldsm4(a[0], a[1], a[2], a[3], ab + toff128(rowA, k0 + kA));
#pragma unroll
        for (int nn = 0; nn < 8; nn++) {
            uint32_t b0, b1, b2, b3;
            ldsm4(b0, b1, b2, b3, bb + toff128(nn * 16 + rowB, k0 + kB));
            mma_f16(acc[2 * nn], a, b0, b1);
            mma_f16(acc[2 * nn + 1], a, b2, b3);
        }
    }

    // ---- epilogue: gout (fp16) + column stats ----
    int quad = lane >> 2;
    int cp = (lane & 3) * 2;
    int lr0 = rowBase + m0 + quad;
    int lr1 = lr0 + 8;
    bool v0 = lr0 < ndst, v1 = lr1 < ndst;
    float* sstat = (float*)(smem + OFF_STAT);

#pragma unroll
    for (int t = 0; t < 16; t++) {
        int c = t * 8 + cp;
        float x0 = acc[t][0], x1 = acc[t][1];
        float y0 = acc[t][2], y1 = acc[t][3];
        if (v0) *(__half2*)(out + (size_t)(goutBase + lr0) * D + c) = __floats2half2_rn(x0, x1);
        if (v1) *(__half2*)(out + (size_t)(goutBase + lr1) * D + c) = __floats2half2_rn(y0, y1);
        float s0 = (v0 ? x0 : 0.f) + (v1 ? y0 : 0.f);
        float s1 = (v0 ? x1 : 0.f) + (v1 ? y1 : 0.f);
        float q0 = (v0 ? x0 * x0 : 0.f) + (v1 ? y0 * y0 : 0.f);
        float q1 = (v0 ? x1 * x1 : 0.f) + (v1 ? y1 * y1 : 0.f);
#pragma unroll
        for (int S = 4; S <= 16; S <<= 1) {
            s0 += __shfl_xor_sync(0xffffffffu, s0, S);
            s1 += __shfl_xor_sync(0xffffffffu, s1, S);
            q0 += __shfl_xor_sync(0xffffffffu, q0, S);
            q1 += __shfl_xor_sync(0xffffffffu, q1, S);
        }
        if (lane < 4) {
            atomicAdd(&sstat[c], s0);
            atomicAdd(&sstat[c + 1], s1);
            atomicAdd(&sstat[128 + c], q0);
            atomicAdd(&sstat[128 + c + 1], q1);
        }
    }
    __syncthreads();
    atomicAdd(&stats[rel * 256 + tid], sstat[tid]);
}

// ---------------- BN finalize (re-zeroes stats for next layer) ----------------
__global__ void k_finalize9(const float* __restrict__ gammaL, const float* __restrict__ betaL) {
    int r = blockIdx.x;
    int c = threadIdx.x;
    float n = (float)c_ndst[r];
    float mu = g_stats[r * 256 + c] / n;
    float var = g_stats[r * 256 + 128 + c] / n - mu * mu;
    float inv = rsqrtf(var + BN_EPS);
    float sc = inv * gammaL[r * D + c];
    g_scale[r * D + c] = sc;
    g_shift[r * D + c] = betaL[r * D + c] - mu * sc;
    g_stats[r * 256 + c] = 0.f;
    g_stats[r * 256 + 128 + c] = 0.f;
}

// ------- fused normalize + 3-rel sum; layer0 -> fp16 feat, layer1 -> fp32 out ---
__global__ void k_fuse_all(const __half* __restrict__ gout,
                           const float4* __restrict__ ra, const float4* __restrict__ rb,
                           const float4* __restrict__ rg, int layer,
                           float4* __restrict__ outF, __half* __restrict__ outH) {
    int i = blockIdx.x * blockDim.x + threadIdx.x;
    if (i >= NTOT * 32) return;
    int row = i >> 5;
    int c4 = i & 31;
    int c = c4 * 4;
    int type = (row < NA) ? 0 : (row < NA + NB) ? 1 : 2;
    int local = row - c_toff[type];
    int r0 = c_rl[type * 3], r1 = c_rl[type * 3 + 1], r2 = c_rl[type * 3 + 2];

    uint2 ha = *(const uint2*)(gout + (size_t)(c_doff[r0] + local) * D + c);
    uint2 hb = *(const uint2*)(gout + (size_t)(c_doff[r1] + local) * D + c);
    uint2 hg = *(const uint2*)(gout + (size_t)(c_doff[r2] + local) * D + c);
    float2 a01 = __half22float2(*(__half2*)&ha.x), a23 = __half22float2(*(__half2*)&ha.y);
    float2 b01 = __half22float2(*(__half2*)&hb.x), b23 = __half22float2(*(__half2*)&hb.y);
    float2 g01 = __half22float2(*(__half2*)&hg.x), g23 = __half22float2(*(__half2*)&hg.y);

    float4 o;
    o.x = a01.x * g_scale[r0 * D + c + 0] + b01.x * g_scale[r1 * D + c + 0] + g01.x * g_scale[r2 * D + c + 0]
        + g_shift[r0 * D + c + 0] + g_shift[r1 * D + c + 0] + g_shift[r2 * D + c + 0];
    o.y = a01.y * g_scale[r0 * D + c + 1] + b01.y * g_scale[r1 * D + c + 1] + g01.y * g_scale[r2 * D + c + 1]
        + g_shift[r0 * D + c + 1] + g_shift[r1 * D + c + 1] + g_shift[r2 * D + c + 1];
    o.z = a23.x * g_scale[r0 * D + c + 2] + b23.x * g_scale[r1 * D + c + 2] + g23.x * g_scale[r2 * D + c + 2]
        + g_shift[r0 * D + c + 2] + g_shift[r1 * D + c + 2] + g_shift[r2 * D + c + 2];
    o.w = a23.y * g_scale[r0 * D + c + 3] + b23.y * g_scale[r1 * D + c + 3] + g23.y * g_scale[r2 * D + c + 3]
        + g_shift[r0 * D + c + 3] + g_shift[r1 * D + c + 3] + g_shift[r2 * D + c + 3];
    if (layer == 1) {
        const float4* rp = (type == 0) ? ra : (type == 1) ? rb : rg;
        float4 rr = rp[(size_t)local * 32 + c4];
        o.x += rr.x; o.y += rr.y; o.z += rr.z; o.w += rr.w;
        outF[i] = o;
    } else {
        ((__half2*)outH)[i * 2] = __floats2half2_rn(o.x, o.y);
        ((__half2*)outH)[i * 2 + 1] = __floats2half2_rn(o.z, o.w);
    }
}

// ---------------- cleanup ----------------
__global__ void k_cleanup() {
    int i = blockIdx.x * blockDim.x + threadIdx.x;
    int n4 = DEG_TOT / 4;
    if (i < n4) {
        ((int4*)g_odeg)[i] = make_int4(0, 0, 0, 0);
        ((int4*)g_ideg)[i] = make_int4(0, 0, 0, 0);
    }
}

// ---------------- host orchestration ----------------
static inline int cdiv(int a, int b) { return (a + b - 1) / b; }

extern "C" void kernel_launch(void* const* d_in, const int* in_sizes, int n_in,
                              void* d_out, int out_size) {
    const float* fa = (const float*)d_in[0];
    const float* fb = (const float*)d_in[1];
    const float* fg = (const float*)d_in[2];
    const float* W = (const float*)d_in[3];
    const float* gamma = (const float*)d_in[5];
    const float* beta = (const float*)d_in[6];

    EdgePtrs E;
    for (int r = 0; r < 9; r++) {
        E.s[r] = (const int*)d_in[7 + 2 * r];
        E.d[r] = (const int*)d_in[8 + 2 * r];
    }

    float* p_stats;
    __half *p_wh, *p_fh, *p_gout;
    cudaGetSymbolAddress((void**)&p_gout, g_gout);
    cudaGetSymbolAddress((void**)&p_stats, g_stats);
    cudaGetSymbolAddress((void**)&p_wh, g_wh);
    cudaGetSymbolAddress((void**)&p_fh, g_fh);

    cudaFuncSetAttribute(k_gemm_fused, cudaFuncAttributeMaxDynamicSharedMemorySize, SMEM_DYN);

    const int TB = 256;

    // 0: W->fp16 + degree count + feat->fp16
    k_prep<<<18 + EBLK + CBLK, TB>>>(E, W, (const float4*)fa, (const float4*)fb,
                                     (const float4*)fg);
    // 1: scan + ns/nd + rowinfo.deg
    k_scan1<<<SCAN_NB, 1024>>>();
    // 2: CSR fill (rowinfo.off)
    k_fill_all<<<cdiv(NE_TOT, TB), TB>>>(E);
    // 3: fused gather+GEMM L0 (ncu target)
    k_gemm_fused<<<NTILES, 256, SMEM_DYN>>>(p_fh, p_wh, 0, p_gout, p_stats);
    // 4: finalize L0
    k_finalize9<<<9, 128>>>(gamma, beta);
    // 5: fuse L0 -> fp16 feat
    k_fuse_all<<<cdiv(NTOT * 32, TB), TB>>>(p_gout, (const float4*)fa, (const float4*)fb,
                                            (const float4*)fg, 0, nullptr, p_fh);
    // 6-8: layer 1
    k_gemm_fused<<<NTILES, 256, SMEM_DYN>>>(p_fh, p_wh, 1, p_gout, p_stats);
    k_finalize9<<<9, 128>>>(gamma + 9 * D, beta + 9 * D);
    k_fuse_all<<<cdiv(NTOT * 32, TB), TB>>>(p_gout, (const float4*)fa, (const float4*)fb,
                                            (const float4*)fg, 1, (float4*)d_out, nullptr);
    // 9: cleanup
    k_cleanup<<<cdiv(DEG_TOT / 4, TB), TB>>>();
}

// round 15
// speedup vs baseline: 1.1824x; 1.1824x over previous
#include <cuda_runtime.h>
#include <cuda_fp16.h>
#include <cstdint>

#define D 128
#define NA 100000
#define NB 150000
#define NG 2000
#define NTOT (NA + NB + NG)      // 252000
#define DEG_TOT 756000
#define NE_TOT 1352000
#define NTILES 5910
#define BN_EPS 1e-5f
#define SCAN_NB ((DEG_TOT + 1023) / 1024)   // 739

#define EBLK ((NE_TOT + 255) / 256)          // 5282
#define CBLK ((NTOT * 32 + 255) / 256)       // 31500

// ---------------- constant boundary tables ----------------
__constant__ int c_doff[10] = {0,150000,250000,252000,352000,354000,504000,604000,754000,756000};
__constant__ int c_soff[10] = {0,100000,250000,350000,352000,502000,504000,604000,754000,756000};
__constant__ int c_eoff[10] = {0,300000,600000,700000,800000,950000,1100000,1200000,1350000,1352000};
__constant__ int c_tbase[10] = {0,1172,1954,1970,2752,2768,3940,4722,5894,5910};
__constant__ int c_stoff[9] = {0, NA, 0, NA + NB, NA, NA + NB, 0, NA, NA + NB};
__constant__ int c_ndst[9] = {NB, NA, NG, NA, NG, NB, NA, NB, NG};
__constant__ int c_rl[9] = {1, 3, 6, 0, 5, 7, 2, 4, 8};
__constant__ int c_toff[3] = {0, NA, NA + NB};

// ---------------- device scratch ----------------
__device__ int g_odeg[DEG_TOT];
__device__ int g_ideg[DEG_TOT];
__device__ int g_offs[DEG_TOT];
__device__ int2 g_rowinfo[DEG_TOT];               // {csr_off (fill), deg (scan1)}
__device__ int g_cursor[DEG_TOT];
__device__ int g_bsum[SCAN_NB];
__device__ int2 g_epack[NE_TOT];                  // {src_byte_off, ns fp32 bits}
__device__ float g_ns[DEG_TOT];
__device__ float g_nd[DEG_TOT];
__device__ __align__(128) __half g_fh[(size_t)NTOT * D];
__device__ __align__(128) __half g_mh[(size_t)NTILES * 16384];
__device__ __align__(128) __half g_gout[(size_t)DEG_TOT * D];
__device__ float g_stats[9 * 2 * D];
__device__ float g_scale[9 * D];
__device__ float g_shift[9 * D];
__device__ __align__(128) __half g_wh[18 * D * D];

struct EdgePtrs { const int* s[9]; const int* d[9]; };

// ---------------- helpers ----------------
__device__ __forceinline__ uint32_t sw128(uint32_t o) { return o ^ ((o >> 3) & 0x70); }
__device__ __forceinline__ uint32_t toff128(uint32_t row, uint32_t k) {
    return ((k >> 6) << 14) + sw128(row * 128 + ((k & 63) << 1));
}
__device__ __forceinline__ uint32_t smem_u32(const void* p) {
    uint32_t a;
    asm("{ .reg .u64 t; cvta.to.shared.u64 t, %1; cvt.u32.u64 %0, t; }" : "=r"(a) : "l"(p));
    return a;
}
__device__ __forceinline__ void ldsm4(uint32_t& r0, uint32_t& r1, uint32_t& r2, uint32_t& r3,
                                      uint32_t addr) {
    asm volatile("ldmatrix.sync.aligned.m8n8.x4.shared.b16 {%0,%1,%2,%3}, [%4];"
                 : "=r"(r0), "=r"(r1), "=r"(r2), "=r"(r3) : "r"(addr));
}
__device__ __forceinline__ void mma_f16(float* d, const uint32_t* a, uint32_t b0, uint32_t b1) {
    asm volatile(
        "mma.sync.aligned.m16n8k16.row.col.f32.f16.f16.f32 "
        "{%0,%1,%2,%3}, {%4,%5,%6,%7}, {%8,%9}, {%0,%1,%2,%3};"
        : "+f"(d[0]), "+f"(d[1]), "+f"(d[2]), "+f"(d[3])
        : "r"(a[0]), "r"(a[1]), "r"(a[2]), "r"(a[3]), "r"(b0), "r"(b1));
}
__device__ __forceinline__ void cpasync16(uint32_t dst, const void* src) {
    asm volatile("cp.async.ca.shared.global [%0], [%1], 16;" :: "r"(dst), "l"(src));
}
__device__ __forceinline__ void acc8(float* acc, const uint4& v, float w) {
    float2 t0 = __half22float2(*(__half2*)&v.x);
    float2 t1 = __half22float2(*(__half2*)&v.y);
    float2 t2 = __half22float2(*(__half2*)&v.z);
    float2 t3 = __half22float2(*(__half2*)&v.w);
    acc[0] += t0.x * w; acc[1] += t0.y * w;
    acc[2] += t1.x * w; acc[3] += t1.y * w;
    acc[4] += t2.x * w; acc[5] += t2.y * w;
    acc[6] += t3.x * w; acc[7] += t3.y * w;
}

// ---------------- launch 0: W->fp16 swizzled + degree count + feat->fp16 -------
__global__ void k_prep(EdgePtrs E, const float* __restrict__ W,
                       const float4* __restrict__ fa4, const float4* __restrict__ fb4,
                       const float4* __restrict__ fg4) {
    if (blockIdx.x < 18) {
        int rel = blockIdx.x;
        const float* w = W + (size_t)rel * D * D;
        char* wh = (char*)g_wh + (size_t)rel * D * D * 2;
        for (int idx = threadIdx.x; idx < D * D; idx += blockDim.x) {
            int k = idx >> 7, n = idx & 127;
            *(__half*)(wh + toff128(n, k)) = __float2half_rn(w[idx]);
        }
        return;
    }
    if (blockIdx.x < 18 + EBLK) {
        int e = (blockIdx.x - 18) * blockDim.x + threadIdx.x;
        if (e >= NE_TOT) return;
        int rel = 0;
#pragma unroll
        for (int r = 1; r < 9; r++) if (e >= c_eoff[r]) rel = r;
        int le = e - c_eoff[rel];
        atomicAdd(&g_odeg[c_soff[rel] + E.s[rel][le]], 1);
        atomicAdd(&g_ideg[c_doff[rel] + E.d[rel][le]], 1);
        return;
    }
    int i = (blockIdx.x - 18 - EBLK) * blockDim.x + threadIdx.x;
    if (i >= NTOT * 32) return;
    int t = (i < NA * 32) ? 0 : (i < (NA + NB) * 32) ? 1 : 2;
    const float4* src = (t == 0) ? fa4 : (t == 1) ? fb4 : fg4;
    int base4 = (t == 0) ? 0 : (t == 1) ? NA * 32 : (NA + NB) * 32;
    float4 v = src[i - base4];
    ((__half2*)g_fh)[i * 2] = __floats2half2_rn(v.x, v.y);
    ((__half2*)g_fh)[i * 2 + 1] = __floats2half2_rn(v.z, v.w);
}

// ---------------- launch 1: scan + ns/nd + rowinfo.deg + cursor/stats zero -----
__global__ void k_scan1() {
    int tid = threadIdx.x;
    int gid = blockIdx.x * 1024 + tid;
    int lane = tid & 31;
    int w = tid >> 5;
    int v = (gid < DEG_TOT) ? g_ideg[gid] : 0;
    if (gid < DEG_TOT) {
        int od = g_odeg[gid];
        g_ns[gid] = (od > 0) ? rsqrtf((float)od) : 0.f;
        g_nd[gid] = (v > 0) ? rsqrtf((float)v) : 0.f;
        g_cursor[gid] = 0;
        g_rowinfo[gid].y = v;
    }
    if (blockIdx.x == 0) {
        for (int i = tid; i < 9 * 256; i += 1024) g_stats[i] = 0.f;
    }
    int inc = v;
#pragma unroll
    for (int s = 1; s < 32; s <<= 1) {
        int x = __shfl_up_sync(0xffffffffu, inc, s);
        if (lane >= s) inc += x;
    }
    __shared__ int wsum[32];
    if (lane == 31) wsum[w] = inc;
    __syncthreads();
    if (w == 0) {
        int x = (lane < 32) ? wsum[lane] : 0;
        int sc = x;
#pragma unroll
        for (int s = 1; s < 32; s <<= 1) {
            int y = __shfl_up_sync(0xffffffffu, sc, s);
            if (lane >= s) sc += y;
        }
        wsum[lane] = sc - x;
    }
    __syncthreads();
    int excl = inc - v + wsum[w];
    if (gid < DEG_TOT) g_offs[gid] = excl;
    if (tid == 1023) g_bsum[blockIdx.x] = excl + v;
}

// ---------------- launch 2: CSR fill (writes rowinfo.off) ----------------
__global__ __launch_bounds__(256)
void k_fill_all(EdgePtrs E) {
    __shared__ int sb[768];
    __shared__ int wsum[8];
    int t = threadIdx.x;
    int base = t * 3;
    int a0 = (base < SCAN_NB) ? g_bsum[base] : 0;
    int a1 = (base + 1 < SCAN_NB) ? g_bsum[base + 1] : 0;
    int a2 = (base + 2 < SCAN_NB) ? g_bsum[base + 2] : 0;
    int tsum = a0 + a1 + a2;
    int lane = t & 31;
    int inc = tsum;
#pragma unroll
    for (int s = 1; s < 32; s <<= 1) {
        int x = __shfl_up_sync(0xffffffffu, inc, s);
        if (lane >= s) inc += x;
    }
    if (lane == 31) wsum[t >> 5] = inc;
    __syncthreads();
    if (t < 8) {
        int x = wsum[t];
        int sc = x;
#pragma unroll
        for (int s = 1; s < 8; s <<= 1) {
            int y = __shfl_up_sync(0xffu, sc, s);
            if (t >= s) sc += y;
        }
        wsum[t] = sc - x;
    }
    __syncthreads();
    int excl = inc - tsum + wsum[t >> 5];
    sb[base] = excl;
    sb[base + 1] = excl + a0;
    sb[base + 2] = excl + a0 + a1;
    __syncthreads();

    int e = blockIdx.x * blockDim.x + t;
    if (e >= NE_TOT) return;
    int rel = 0;
#pragma unroll
    for (int r = 1; r < 9; r++) if (e >= c_eoff[r]) rel = r;
    int le = e - c_eoff[rel];
    int ss = E.s[rel][le];
    int dd = E.d[rel][le];
    int gslot = c_doff[rel] + dd;
    int ofin = g_offs[gslot] + sb[gslot >> 10];
    int pos = ofin + atomicAdd(&g_cursor[gslot], 1);
    g_epack[pos] = make_int2(ss * 256, __float_as_int(g_ns[c_soff[rel] + ss]));
    g_rowinfo[gslot].x = ofin;
}

// ------ gather: 4 rows/warp (8 lanes/row, 32B/lane), fp32 accum -> fp16 tiles ---
__global__ void k_gather_all(const __half* __restrict__ fh) {
    int lane = threadIdx.x & 31;
    int l8 = lane & 7;
    int row = (blockIdx.x * (blockDim.x >> 5) + (threadIdx.x >> 5)) * 4 + (lane >> 3);
    if (row >= DEG_TOT) return;
    int rel = 0;
#pragma unroll
    for (int r = 1; r < 9; r++) if (row >= c_doff[r]) rel = r;
    int lrow = row - c_doff[rel];
    const char* fbase = (const char*)fh + (size_t)c_stoff[rel] * 256 + l8 * 32;

    int2 ri = __ldg(&g_rowinfo[row]);
    int dg = ri.y;
    float acc[16];
#pragma unroll
    for (int j = 0; j < 16; j++) acc[j] = 0.f;
    if (dg > 0) {
        const int2* ep = g_epack + ri.x;
        int e = 0;
        for (; e + 2 <= dg; e += 2) {
            int2 p0 = __ldg(ep + e);
            int2 p1 = __ldg(ep + e + 1);
            uint4 v0a = __ldg((const uint4*)(fbase + (uint32_t)p0.x));
            uint4 v0b = __ldg((const uint4*)(fbase + (uint32_t)p0.x + 16));
            uint4 v1a = __ldg((const uint4*)(fbase + (uint32_t)p1.x));
            uint4 v1b = __ldg((const uint4*)(fbase + (uint32_t)p1.x + 16));
            float w0 = __int_as_float(p0.y), w1 = __int_as_float(p1.y);
            acc8(acc, v0a, w0);
            acc8(acc + 8, v0b, w0);
            acc8(acc, v1a, w1);
            acc8(acc + 8, v1b, w1);
        }
        if (e < dg) {
            int2 p0 = __ldg(ep + e);
            uint4 v0a = __ldg((const uint4*)(fbase + (uint32_t)p0.x));
            uint4 v0b = __ldg((const uint4*)(fbase + (uint32_t)p0.x + 16));
            float w0 = __int_as_float(p0.y);
            acc8(acc, v0a, w0);
            acc8(acc + 8, v0b, w0);
        }
        float ndv = __ldg(g_nd + row);
#pragma unroll
        for (int j = 0; j < 16; j++) acc[j] *= ndv;
    }

    uint4 pk0, pk1;
    *(__half2*)&pk0.x = __floats2half2_rn(acc[0], acc[1]);
    *(__half2*)&pk0.y = __floats2half2_rn(acc[2], acc[3]);
    *(__half2*)&pk0.z = __floats2half2_rn(acc[4], acc[5]);
    *(__half2*)&pk0.w = __floats2half2_rn(acc[6], acc[7]);
    *(__half2*)&pk1.x = __floats2half2_rn(acc[8], acc[9]);
    *(__half2*)&pk1.y = __floats2half2_rn(acc[10], acc[11]);
    *(__half2*)&pk1.z = __floats2half2_rn(acc[12], acc[13]);
    *(__half2*)&pk1.w = __floats2half2_rn(acc[14], acc[15]);

    size_t tile = (size_t)c_tbase[rel] + (lrow >> 7);
    uint32_t ir = lrow & 127;
    char* bh = (char*)g_mh + tile * 32768;
    uint32_t half_tile = (uint32_t)(l8 >> 2) << 14;
    uint32_t base = ir * 128 + (l8 & 3) * 32;
    *(uint4*)(bh + half_tile + sw128(base)) = pk0;
    *(uint4*)(bh + half_tile + sw128(base + 16)) = pk1;
}

// ------- batched GEMM: 32x64 warp tiles (4Mx2N), single fp16 product + stats ----
#define OFF_A    0
#define OFF_B    32768
#define OFF_STAT 65536
#define SMEM_DYN (65536 + 1024 + 1024)

__global__ __launch_bounds__(256, 2)
void k_gemm_all(const __half* __restrict__ mh, const __half* __restrict__ whAll,
                int layer, __half* __restrict__ out, float* __restrict__ stats) {
    extern __shared__ char smem_raw[];
    char* smem = (char*)((((uintptr_t)smem_raw) + 1023) & ~(uintptr_t)1023);
    uint32_t sa = smem_u32(smem);
    int tid = threadIdx.x;
    int lane = tid & 31;
    int wid = tid >> 5;
    int bid = blockIdx.x;

    int rel = 0;
#pragma unroll
    for (int r = 1; r < 9; r++) if (bid >= c_tbase[r]) rel = r;
    int rowBase = (bid - c_tbase[rel]) * 128;
    int ndst = c_doff[rel + 1] - c_doff[rel];
    int goutBase = c_doff[rel];

    ((float*)(smem + OFF_STAT))[tid] = 0.f;
    {
        const char* sA = (const char*)mh + (size_t)bid * 32768;
        const char* sB = (const char*)whAll + (size_t)(layer * 9 + rel) * 32768;
#pragma unroll
        for (int i = tid; i < 2048; i += 256) {
            cpasync16(sa + OFF_A + i * 16, sA + i * 16);
            cpasync16(sa + OFF_B + i * 16, sB + i * 16);
        }
        asm volatile("cp.async.commit_group;" ::: "memory");
        asm volatile("cp.async.wait_group 0;" ::: "memory");
    }
    __syncthreads();

    // warp tile: 32 rows x 64 cols.  4 M-warps x 2 N-warps.
    int m0 = (wid & 3) * 32;
    int n0 = (wid >> 2) * 64;

    float acc[2][8][4];
#pragma unroll
    for (int ai = 0; ai < 2; ai++)
#pragma unroll
        for (int nj = 0; nj < 8; nj++)
#pragma unroll
            for (int j = 0; j < 4; j++) acc[ai][nj][j] = 0.f;

    uint32_t rowAl = lane & 15;
    uint32_t kA = (lane >> 4) << 3;
    uint32_t rowB = (lane & 7) + ((lane >> 4) << 3);
    uint32_t kB = ((lane >> 3) & 1) << 3;

    uint32_t ab = sa + OFF_A;
    uint32_t bb = sa + OFF_B;
#pragma unroll
    for (int k0 = 0; k0 < 128; k0 += 16) {
        uint32_t a0[4], a1[4];
        ldsm4(a0[0], a0[1], a0[2], a0[3], ab + toff128(m0 + rowAl, k0 + kA));
        ldsm4(a1[0], a1[1], a1[2], a1[3], ab + toff128(m0 + 16 + rowAl, k0 + kA));
#pragma unroll
        for (int nb = 0; nb < 4; nb++) {
            uint32_t b0, b1, b2, b3;
            ldsm4(b0, b1, b2, b3, bb + toff128(n0 + nb * 16 + rowB, k0 + kB));
            mma_f16(acc[0][2 * nb], a0, b0, b1);
            mma_f16(acc[0][2 * nb + 1], a0, b2, b3);
            mma_f16(acc[1][2 * nb], a1, b0, b1);
            mma_f16(acc[1][2 * nb + 1], a1, b2, b3);
        }
    }

    // epilogue: gout (fp16) + column stats
    int quad = lane >> 2;
    int cp = (lane & 3) * 2;
    float* sstat = (float*)(smem + OFF_STAT);

#pragma unroll
    for (int nj = 0; nj < 8; nj++) {
        int c = n0 + nj * 8 + cp;
        float s0 = 0.f, s1 = 0.f, q0 = 0.f, q1 = 0.f;
#pragma unroll
        for (int ai = 0; ai < 2; ai++) {
            int lr0 = rowBase + m0 + ai * 16 + quad;
            int lr1 = lr0 + 8;
            bool v0 = lr0 < ndst, v1 = lr1 < ndst;
            float x0 = acc[ai][nj][0], x1 = acc[ai][nj][1];
            float y0 = acc[ai][nj][2], y1 = acc[ai][nj][3];
            if (v0) *(__half2*)(out + (size_t)(goutBase + lr0) * D + c) = __floats2half2_rn(x0, x1);
            if (v1) *(__half2*)(out + (size_t)(goutBase + lr1) * D + c) = __floats2half2_rn(y0, y1);
            s0 += (v0 ? x0 : 0.f) + (v1 ? y0 : 0.f);
            s1 += (v0 ? x1 : 0.f) + (v1 ? y1 : 0.f);
            q0 += (v0 ? x0 * x0 : 0.f) + (v1 ? y0 * y0 : 0.f);
            q1 += (v0 ? x1 * x1 : 0.f) + (v1 ? y1 * y1 : 0.f);
        }
#pragma unroll
        for (int S = 4; S <= 16; S <<= 1) {
            s0 += __shfl_xor_sync(0xffffffffu, s0, S);
            s1 += __shfl_xor_sync(0xffffffffu, s1, S);
            q0 += __shfl_xor_sync(0xffffffffu, q0, S);
            q1 += __shfl_xor_sync(0xffffffffu, q1, S);
        }
        if (lane < 4) {
            atomicAdd(&sstat[c], s0);
            atomicAdd(&sstat[c + 1], s1);
            atomicAdd(&sstat[128 + c], q0);
            atomicAdd(&sstat[128 + c + 1], q1);
        }
    }
    __syncthreads();
    atomicAdd(&stats[rel * 256 + tid], sstat[tid]);
}

// ---------------- BN finalize (re-zeroes stats for next layer) ----------------
__global__ void k_finalize9(const float* __restrict__ gammaL, const float* __restrict__ betaL) {
    int r = blockIdx.x;
    int c = threadIdx.x;
    float n = (float)c_ndst[r];
    float mu = g_stats[r * 256 + c] / n;
    float var = g_stats[r * 256 + 128 + c] / n - mu * mu;
    float inv = rsqrtf(var + BN_EPS);
    float sc = inv * gammaL[r * D + c];
    g_scale[r * D + c] = sc;
    g_shift[r * D + c] = betaL[r * D + c] - mu * sc;
    g_stats[r * 256 + c] = 0.f;
    g_stats[r * 256 + 128 + c] = 0.f;
}

// ------- fused normalize + 3-rel sum; layer0 -> fp16 feat, layer1 -> fp32 out ---
__global__ void k_fuse_all(const __half* __restrict__ gout,
                           const float4* __restrict__ ra, const float4* __restrict__ rb,
                           const float4* __restrict__ rg, int layer,
                           float4* __restrict__ outF, __half* __restrict__ outH) {
    int i = blockIdx.x * blockDim.x + threadIdx.x;
    if (i >= NTOT * 32) return;
    int row = i >> 5;
    int c4 = i & 31;
    int c = c4 * 4;
    int type = (row < NA) ? 0 : (row < NA + NB) ? 1 : 2;
    int local = row - c_toff[type];
    int r0 = c_rl[type * 3], r1 = c_rl[type * 3 + 1], r2 = c_rl[type * 3 + 2];

    uint2 ha = *(const uint2*)(gout + (size_t)(c_doff[r0] + local) * D + c);
    uint2 hb = *(const uint2*)(gout + (size_t)(c_doff[r1] + local) * D + c);
    uint2 hg = *(const uint2*)(gout + (size_t)(c_doff[r2] + local) * D + c);
    float2 a01 = __half22float2(*(__half2*)&ha.x), a23 = __half22float2(*(__half2*)&ha.y);
    float2 b01 = __half22float2(*(__half2*)&hb.x), b23 = __half22float2(*(__half2*)&hb.y);
    float2 g01 = __half22float2(*(__half2*)&hg.x), g23 = __half22float2(*(__half2*)&hg.y);

    float4 o;
    o.x = a01.x * g_scale[r0 * D + c + 0] + b01.x * g_scale[r1 * D + c + 0] + g01.x * g_scale[r2 * D + c + 0]
        + g_shift[r0 * D + c + 0] + g_shift[r1 * D + c + 0] + g_shift[r2 * D + c + 0];
    o.y = a01.y * g_scale[r0 * D + c + 1] + b01.y * g_scale[r1 * D + c + 1] + g01.y * g_scale[r2 * D + c + 1]
        + g_shift[r0 * D + c + 1] + g_shift[r1 * D + c + 1] + g_shift[r2 * D + c + 1];
    o.z = a23.x * g_scale[r0 * D + c + 2] + b23.x * g_scale[r1 * D + c + 2] + g23.x * g_scale[r2 * D + c + 2]
        + g_shift[r0 * D + c + 2] + g_shift[r1 * D + c + 2] + g_shift[r2 * D + c + 2];
    o.w = a23.y * g_scale[r0 * D + c + 3] + b23.y * g_scale[r1 * D + c + 3] + g23.y * g_scale[r2 * D + c + 3]
        + g_shift[r0 * D + c + 3] + g_shift[r1 * D + c + 3] + g_shift[r2 * D + c + 3];
    if (layer == 1) {
        const float4* rp = (type == 0) ? ra : (type == 1) ? rb : rg;
        float4 rr = rp[(size_t)local * 32 + c4];
        o.x += rr.x; o.y += rr.y; o.z += rr.z; o.w += rr.w;
        outF[i] = o;
    } else {
        ((__half2*)outH)[i * 2] = __floats2half2_rn(o.x, o.y);
        ((__half2*)outH)[i * 2 + 1] = __floats2half2_rn(o.z, o.w);
    }
}

// ---------------- cleanup ----------------
__global__ void k_cleanup() {
    int i = blockIdx.x * blockDim.x + threadIdx.x;
    int n4 = DEG_TOT / 4;
    if (i < n4) {
        ((int4*)g_odeg)[i] = make_int4(0, 0, 0, 0);
        ((int4*)g_ideg)[i] = make_int4(0, 0, 0, 0);
    }
}

// ---------------- host orchestration ----------------
static inline int cdiv(int a, int b) { return (a + b - 1) / b; }

extern "C" void kernel_launch(void* const* d_in, const int* in_sizes, int n_in,
                              void* d_out, int out_size) {
    const float* fa = (const float*)d_in[0];
    const float* fb = (const float*)d_in[1];
    const float* fg = (const float*)d_in[2];
    const float* W = (const float*)d_in[3];
    const float* gamma = (const float*)d_in[5];
    const float* beta = (const float*)d_in[6];

    EdgePtrs E;
    for (int r = 0; r < 9; r++) {
        E.s[r] = (const int*)d_in[7 + 2 * r];
        E.d[r] = (const int*)d_in[8 + 2 * r];
    }

    float* p_stats;
    __half *p_wh, *p_mh, *p_fh, *p_gout;
    cudaGetSymbolAddress((void**)&p_gout, g_gout);
    cudaGetSymbolAddress((void**)&p_stats, g_stats);
    cudaGetSymbolAddress((void**)&p_wh, g_wh);
    cudaGetSymbolAddress((void**)&p_mh, g_mh);
    cudaGetSymbolAddress((void**)&p_fh, g_fh);

    cudaFuncSetAttribute(k_gemm_all, cudaFuncAttributeMaxDynamicSharedMemorySize, SMEM_DYN);

    const int TB = 256;
    const int GGRID = DEG_TOT / 32;   // 4 rows per warp, 8 warps per block

    // 0: W->fp16 + degree count + feat->fp16
    k_prep<<<18 + EBLK + CBLK, TB>>>(E, W, (const float4*)fa, (const float4*)fb,
                                     (const float4*)fg);
    // 1: scan + ns/nd + rowinfo.deg
    k_scan1<<<SCAN_NB, 1024>>>();
    // 2: CSR fill (rowinfo.off)
    k_fill_all<<<cdiv(NE_TOT, TB), TB>>>(E);
    // 3: gather L0 (ncu target)
    k_gather_all<<<GGRID, TB>>>(p_fh);
    // 4: GEMM L0
    k_gemm_all<<<NTILES, 256, SMEM_DYN>>>(p_mh, p_wh, 0, p_gout, p_stats);
    // 5: finalize L0
    k_finalize9<<<9, 128>>>(gamma, beta);
    // 6: fuse L0 -> fp16 feat
    k_fuse_all<<<cdiv(NTOT * 32, TB), TB>>>(p_gout, (const float4*)fa, (const float4*)fb,
                                            (const float4*)fg, 0, nullptr, p_fh);
    // 7-10: layer 1
    k_gather_all<<<GGRID, TB>>>(p_fh);
    k_gemm_all<<<NTILES, 256, SMEM_DYN>>>(p_mh, p_wh, 1, p_gout, p_stats);
    k_finalize9<<<9, 128>>>(gamma + 9 * D, beta + 9 * D);
    k_fuse_all<<<cdiv(NTOT * 32, TB), TB>>>(p_gout, (const float4*)fa, (const float4*)fb,
                                            (const float4*)fg, 1, (float4*)d_out, nullptr);
    // 11: cleanup
    k_cleanup<<<cdiv(DEG_TOT / 4, TB), TB>>>();
}

// round 16
// speedup vs baseline: 1.3246x; 1.1203x over previous
#include <cuda_runtime.h>
#include <cuda_fp16.h>
#include <cstdint>

#define D 128
#define NA 100000
#define NB 150000
#define NG 2000
#define NTOT (NA + NB + NG)      // 252000
#define DEG_TOT 756000
#define NE_TOT 1352000
#define NTILES 5910
#define BN_EPS 1e-5f
#define SCAN_NB ((DEG_TOT + 1023) / 1024)   // 739

#define EBLK ((NE_TOT + 255) / 256)          // 5282
#define CBLK ((NTOT * 32 + 255) / 256)       // 31500

// ---------------- constant boundary tables ----------------
__constant__ int c_doff[10] = {0,150000,250000,252000,352000,354000,504000,604000,754000,756000};
__constant__ int c_soff[10] = {0,100000,250000,350000,352000,502000,504000,604000,754000,756000};
__constant__ int c_eoff[10] = {0,300000,600000,700000,800000,950000,1100000,1200000,1350000,1352000};
__constant__ int c_tbase[10] = {0,1172,1954,1970,2752,2768,3940,4722,5894,5910};
__constant__ int c_stoff[9] = {0, NA, 0, NA + NB, NA, NA + NB, 0, NA, NA + NB};
__constant__ int c_ndst[9] = {NB, NA, NG, NA, NG, NB, NA, NB, NG};
__constant__ int c_rl[9] = {1, 3, 6, 0, 5, 7, 2, 4, 8};
__constant__ int c_toff[3] = {0, NA, NA + NB};

// ---------------- device scratch ----------------
__device__ int g_odeg[DEG_TOT];
__device__ int g_ideg[DEG_TOT];
__device__ int g_offs[DEG_TOT];
__device__ int2 g_rowinfo[DEG_TOT];               // {csr_off (fill), deg (scan1)}
__device__ int g_cursor[DEG_TOT];
__device__ int g_bsum[SCAN_NB];
__device__ int2 g_epack[NE_TOT];                  // {src_byte_off, ns fp32 bits}
__device__ float g_ns[DEG_TOT];
__device__ float g_nd[DEG_TOT];
__device__ __align__(128) __half g_fh[(size_t)NTOT * D];
__device__ __align__(128) __half g_gout[(size_t)DEG_TOT * D];
__device__ float g_stats[9 * 2 * D];
__device__ float g_scale[9 * D];
__device__ float g_shift[9 * D];
__device__ __align__(128) __half g_wh[18 * D * D];

struct EdgePtrs { const int* s[9]; const int* d[9]; };

// ---------------- helpers ----------------
__device__ __forceinline__ uint32_t sw128(uint32_t o) { return o ^ ((o >> 3) & 0x70); }
__device__ __forceinline__ uint32_t toff128(uint32_t row, uint32_t k) {
    return ((k >> 6) << 14) + sw128(row * 128 + ((k & 63) << 1));
}
__device__ __forceinline__ uint32_t smem_u32(const void* p) {
    uint32_t a;
    asm("{ .reg .u64 t; cvta.to.shared.u64 t, %1; cvt.u32.u64 %0, t; }" : "=r"(a) : "l"(p));
    return a;
}
__device__ __forceinline__ void ldsm4(uint32_t& r0, uint32_t& r1, uint32_t& r2, uint32_t& r3,
                                      uint32_t addr) {
    asm volatile("ldmatrix.sync.aligned.m8n8.x4.shared.b16 {%0,%1,%2,%3}, [%4];"
                 : "=r"(r0), "=r"(r1), "=r"(r2), "=r"(r3) : "r"(addr));
}
__device__ __forceinline__ void mma_f16(float* d, const uint32_t* a, uint32_t b0, uint32_t b1) {
    asm volatile(
        "mma.sync.aligned.m16n8k16.row.col.f32.f16.f16.f32 "
        "{%0,%1,%2,%3}, {%4,%5,%6,%7}, {%8,%9}, {%0,%1,%2,%3};"
        : "+f"(d[0]), "+f"(d[1]), "+f"(d[2]), "+f"(d[3])
        : "r"(a[0]), "r"(a[1]), "r"(a[2]), "r"(a[3]), "r"(b0), "r"(b1));
}
__device__ __forceinline__ void cpasync16(uint32_t dst, const void* src) {
    asm volatile("cp.async.ca.shared.global [%0], [%1], 16;" :: "r"(dst), "l"(src));
}
__device__ __forceinline__ void acc8(float* acc, const uint4& v, float w) {
    float2 t0 = __half22float2(*(__half2*)&v.x);
    float2 t1 = __half22float2(*(__half2*)&v.y);
    float2 t2 = __half22float2(*(__half2*)&v.z);
    float2 t3 = __half22float2(*(__half2*)&v.w);
    acc[0] += t0.x * w; acc[1] += t0.y * w;
    acc[2] += t1.x * w; acc[3] += t1.y * w;
    acc[4] += t2.x * w; acc[5] += t2.y * w;
    acc[6] += t3.x * w; acc[7] += t3.y * w;
}

// ---------------- launch 0: W->fp16 swizzled + degree count + feat->fp16 -------
__global__ void k_prep(EdgePtrs E, const float* __restrict__ W,
                       const float4* __restrict__ fa4, const float4* __restrict__ fb4,
                       const float4* __restrict__ fg4) {
    if (blockIdx.x < 18) {
        int rel = blockIdx.x;
        const float* w = W + (size_t)rel * D * D;
        char* wh = (char*)g_wh + (size_t)rel * D * D * 2;
        for (int idx = threadIdx.x; idx < D * D; idx += blockDim.x) {
            int k = idx >> 7, n = idx & 127;
            *(__half*)(wh + toff128(n, k)) = __float2half_rn(w[idx]);
        }
        return;
    }
    if (blockIdx.x < 18 + EBLK) {
        int e = (blockIdx.x - 18) * blockDim.x + threadIdx.x;
        if (e >= NE_TOT) return;
        int rel = 0;
#pragma unroll
        for (int r = 1; r < 9; r++) if (e >= c_eoff[r]) rel = r;
        int le = e - c_eoff[rel];
        atomicAdd(&g_odeg[c_soff[rel] + E.s[rel][le]], 1);
        atomicAdd(&g_ideg[c_doff[rel] + E.d[rel][le]], 1);
        return;
    }
    int i = (blockIdx.x - 18 - EBLK) * blockDim.x + threadIdx.x;
    if (i >= NTOT * 32) return;
    int t = (i < NA * 32) ? 0 : (i < (NA + NB) * 32) ? 1 : 2;
    const float4* src = (t == 0) ? fa4 : (t == 1) ? fb4 : fg4;
    int base4 = (t == 0) ? 0 : (t == 1) ? NA * 32 : (NA + NB) * 32;
    float4 v = src[i - base4];
    ((__half2*)g_fh)[i * 2] = __floats2half2_rn(v.x, v.y);
    ((__half2*)g_fh)[i * 2 + 1] = __floats2half2_rn(v.z, v.w);
}

// ---------------- launch 1: scan + ns/nd + rowinfo.deg + cursor/stats zero -----
__global__ void k_scan1() {
    int tid = threadIdx.x;
    int gid = blockIdx.x * 1024 + tid;
    int lane = tid & 31;
    int w = tid >> 5;
    int v = (gid < DEG_TOT) ? g_ideg[gid] : 0;
    if (gid < DEG_TOT) {
        int od = g_odeg[gid];
        g_ns[gid] = (od > 0) ? rsqrtf((float)od) : 0.f;
        g_nd[gid] = (v > 0) ? rsqrtf((float)v) : 0.f;
        g_cursor[gid] = 0;
        g_rowinfo[gid].y = v;
    }
    if (blockIdx.x == 0) {
        for (int i = tid; i < 9 * 256; i += 1024) g_stats[i] = 0.f;
    }
    int inc = v;
#pragma unroll
    for (int s = 1; s < 32; s <<= 1) {
        int x = __shfl_up_sync(0xffffffffu, inc, s);
        if (lane >= s) inc += x;
    }
    __shared__ int wsum[32];
    if (lane == 31) wsum[w] = inc;
    __syncthreads();
    if (w == 0) {
        int x = (lane < 32) ? wsum[lane] : 0;
        int sc = x;
#pragma unroll
        for (int s = 1; s < 32; s <<= 1) {
            int y = __shfl_up_sync(0xffffffffu, sc, s);
            if (lane >= s) sc += y;
        }
        wsum[lane] = sc - x;
    }
    __syncthreads();
    int excl = inc - v + wsum[w];
    if (gid < DEG_TOT) g_offs[gid] = excl;
    if (tid == 1023) g_bsum[blockIdx.x] = excl + v;
}

// ---------------- launch 2: CSR fill (writes rowinfo.off) ----------------
__global__ __launch_bounds__(256)
void k_fill_all(EdgePtrs E) {
    __shared__ int sb[768];
    __shared__ int wsum[8];
    int t = threadIdx.x;
    int base = t * 3;
    int a0 = (base < SCAN_NB) ? g_bsum[base] : 0;
    int a1 = (base + 1 < SCAN_NB) ? g_bsum[base + 1] : 0;
    int a2 = (base + 2 < SCAN_NB) ? g_bsum[base + 2] : 0;
    int tsum = a0 + a1 + a2;
    int lane = t & 31;
    int inc = tsum;
#pragma unroll
    for (int s = 1; s < 32; s <<= 1) {
        int x = __shfl_up_sync(0xffffffffu, inc, s);
        if (lane >= s) inc += x;
    }
    if (lane == 31) wsum[t >> 5] = inc;
    __syncthreads();
    if (t < 8) {
        int x = wsum[t];
        int sc = x;
#pragma unroll
        for (int s = 1; s < 8; s <<= 1) {
            int y = __shfl_up_sync(0xffu, sc, s);
            if (t >= s) sc += y;
        }
        wsum[t] = sc - x;
    }
    __syncthreads();
    int excl = inc - tsum + wsum[t >> 5];
    sb[base] = excl;
    sb[base + 1] = excl + a0;
    sb[base + 2] = excl + a0 + a1;
    __syncthreads();

    int e = blockIdx.x * blockDim.x + t;
    if (e >= NE_TOT) return;
    int rel = 0;
#pragma unroll
    for (int r = 1; r < 9; r++) if (e >= c_eoff[r]) rel = r;
    int le = e - c_eoff[rel];
    int ss = E.s[rel][le];
    int dd = E.d[rel][le];
    int gslot = c_doff[rel] + dd;
    int ofin = g_offs[gslot] + sb[gslot >> 10];
    int pos = ofin + atomicAdd(&g_cursor[gslot], 1);
    g_epack[pos] = make_int2(ss * 256, __float_as_int(g_ns[c_soff[rel] + ss]));
    g_rowinfo[gslot].x = ofin;
}

// ------- fused gather + GEMM (512 thr, 32x32 warp tiles) + stats ---------------
#define OFF_A    0
#define OFF_B    32768
#define OFF_STAT 65536
#define SMEM_DYN (65536 + 1024 + 1024)

__global__ __launch_bounds__(512, 2)
void k_gemm_fused(const __half* __restrict__ fh, const __half* __restrict__ whAll,
                  int layer, __half* __restrict__ out, float* __restrict__ stats) {
    extern __shared__ char smem_raw[];
    char* smem = (char*)((((uintptr_t)smem_raw) + 1023) & ~(uintptr_t)1023);
    uint32_t sa = smem_u32(smem);
    int tid = threadIdx.x;
    int lane = tid & 31;
    int wid = tid >> 5;        // 0..15
    int bid = blockIdx.x;

    int rel = 0;
#pragma unroll
    for (int r = 1; r < 9; r++) if (bid >= c_tbase[r]) rel = r;
    int rowBase = (bid - c_tbase[rel]) * 128;
    int ndst = c_doff[rel + 1] - c_doff[rel];
    int goutBase = c_doff[rel];

    // prefetch B while gathering A
    {
        const char* sB = (const char*)whAll + (size_t)(layer * 9 + rel) * 32768;
#pragma unroll
        for (int i = tid; i < 2048; i += 512) cpasync16(sa + OFF_B + i * 16, sB + i * 16);
        asm volatile("cp.async.commit_group;" ::: "memory");
    }
    if (tid < 256) ((float*)(smem + OFF_STAT))[tid] = 0.f;

    // ---- gather phase: quarter-warp per row, 64 rows/iter, 2 iters ----
    {
        int l8 = lane & 7;
        const char* fbase = (const char*)fh + (size_t)c_stoff[rel] * 256 + l8 * 32;
        char* atile = smem + OFF_A;
        uint32_t half_tile = (uint32_t)(l8 >> 2) << 14;
        uint32_t colb = (l8 & 3) * 32;
#pragma unroll 1
        for (int it = 0; it < 2; it++) {
            int lrow = it * 64 + wid * 4 + (lane >> 3);
            int grow = rowBase + lrow;
            float acc[16];
#pragma unroll
            for (int j = 0; j < 16; j++) acc[j] = 0.f;
            if (grow < ndst) {
                int gslot = goutBase + grow;
                int2 ri = __ldg(&g_rowinfo[gslot]);
                int dg = ri.y;
                if (dg > 0) {
                    const int2* ep = g_epack + ri.x;
                    int e = 0;
                    for (; e + 2 <= dg; e += 2) {
                        int2 p0 = __ldg(ep + e);
                        int2 p1 = __ldg(ep + e + 1);
                        uint4 v0a = __ldg((const uint4*)(fbase + (uint32_t)p0.x));
                        uint4 v0b = __ldg((const uint4*)(fbase + (uint32_t)p0.x + 16));
                        uint4 v1a = __ldg((const uint4*)(fbase + (uint32_t)p1.x));
                        uint4 v1b = __ldg((const uint4*)(fbase + (uint32_t)p1.x + 16));
                        float w0 = __int_as_float(p0.y), w1 = __int_as_float(p1.y);
                        acc8(acc, v0a, w0);
                        acc8(acc + 8, v0b, w0);
                        acc8(acc, v1a, w1);
                        acc8(acc + 8, v1b, w1);
                    }
                    if (e < dg) {
                        int2 p0 = __ldg(ep + e);
                        uint4 v0a = __ldg((const uint4*)(fbase + (uint32_t)p0.x));
                        uint4 v0b = __ldg((const uint4*)(fbase + (uint32_t)p0.x + 16));
                        float w0 = __int_as_float(p0.y);
                        acc8(acc, v0a, w0);
                        acc8(acc + 8, v0b, w0);
                    }
                    float ndv = __ldg(g_nd + gslot);
#pragma unroll
                    for (int j = 0; j < 16; j++) acc[j] *= ndv;
                }
            }
            uint4 pk0, pk1;
            *(__half2*)&pk0.x = __floats2half2_rn(acc[0], acc[1]);
            *(__half2*)&pk0.y = __floats2half2_rn(acc[2], acc[3]);
            *(__half2*)&pk0.z = __floats2half2_rn(acc[4], acc[5]);
            *(__half2*)&pk0.w = __floats2half2_rn(acc[6], acc[7]);
            *(__half2*)&pk1.x = __floats2half2_rn(acc[8], acc[9]);
            *(__half2*)&pk1.y = __floats2half2_rn(acc[10], acc[11]);
            *(__half2*)&pk1.z = __floats2half2_rn(acc[12], acc[13]);
            *(__half2*)&pk1.w = __floats2half2_rn(acc[14], acc[15]);
            uint32_t rb = (uint32_t)lrow * 128 + colb;
            *(uint4*)(atile + half_tile + sw128(rb)) = pk0;
            *(uint4*)(atile + half_tile + sw128(rb + 16)) = pk1;
        }
    }

    asm volatile("cp.async.wait_group 0;" ::: "memory");
    __syncthreads();

    // ---- GEMM mainloop: warp tile 32 rows x 32 cols (4M x 4N warps) ----
    int m0 = (wid & 3) * 32;
    int n0 = (wid >> 2) * 32;

    float acc[2][4][4];
#pragma unroll
    for (int ai = 0; ai < 2; ai++)
#pragma unroll
        for (int nj = 0; nj < 4; nj++)
#pragma unroll
            for (int j = 0; j < 4; j++) acc[ai][nj][j] = 0.f;

    uint32_t rowAl = lane & 15;
    uint32_t kA = (lane >> 4) << 3;
    uint32_t rowB = (lane & 7) + ((lane >> 4) << 3);
    uint32_t kB = ((lane >> 3) & 1) << 3;

    uint32_t ab = sa + OFF_A;
    uint32_t bb = sa + OFF_B;
#pragma unroll
    for (int k0 = 0; k0 < 128; k0 += 16) {
        uint32_t a0[4], a1[4];
        ldsm4(a0[0], a0[1], a0[2], a0[3], ab + toff128(m0 + rowAl, k0 + kA));
        ldsm4(a1[0], a1[1], a1[2], a1[3], ab + toff128(m0 + 16 + rowAl, k0 + kA));
#pragma unroll
        for (int nb = 0; nb < 2; nb++) {
            uint32_t b0, b1, b2, b3;
            ldsm4(b0, b1, b2, b3, bb + toff128(n0 + nb * 16 + rowB, k0 + kB));
            mma_f16(acc[0][2 * nb], a0, b0, b1);
            mma_f16(acc[0][2 * nb + 1], a0, b2, b3);
            mma_f16(acc[1][2 * nb], a1, b0, b1);
            mma_f16(acc[1][2 * nb + 1], a1, b2, b3);
        }
    }

    // ---- epilogue: gout (fp16) + column stats ----
    int quad = lane >> 2;
    int cp = (lane & 3) * 2;
    float* sstat = (float*)(smem + OFF_STAT);

#pragma unroll
    for (int nj = 0; nj < 4; nj++) {
        int c = n0 + nj * 8 + cp;
        float s0 = 0.f, s1 = 0.f, q0 = 0.f, q1 = 0.f;
#pragma unroll
        for (int ai = 0; ai < 2; ai++) {
            int lr0 = rowBase + m0 + ai * 16 + quad;
            int lr1 = lr0 + 8;
            bool v0 = lr0 < ndst, v1 = lr1 < ndst;
            float x0 = acc[ai][nj][0], x1 = acc[ai][nj][1];
            float y0 = acc[ai][nj][2], y1 = acc[ai][nj][3];
            if (v0) *(__half2*)(out + (size_t)(goutBase + lr0) * D + c) = __floats2half2_rn(x0, x1);
            if (v1) *(__half2*)(out + (size_t)(goutBase + lr1) * D + c) = __floats2half2_rn(y0, y1);
            s0 += (v0 ? x0 : 0.f) + (v1 ? y0 : 0.f);
            s1 += (v0 ? x1 : 0.f) + (v1 ? y1 : 0.f);
            q0 += (v0 ? x0 * x0 : 0.f) + (v1 ? y0 * y0 : 0.f);
            q1 += (v0 ? x1 * x1 : 0.f) + (v1 ? y1 * y1 : 0.f);
        }
#pragma unroll
        for (int S = 4; S <= 16; S <<= 1) {
            s0 += __shfl_xor_sync(0xffffffffu, s0, S);
            s1 += __shfl_xor_sync(0xffffffffu, s1, S);
            q0 += __shfl_xor_sync(0xffffffffu, q0, S);
            q1 += __shfl_xor_sync(0xffffffffu, q1, S);
        }
        if (lane < 4) {
            atomicAdd(&sstat[c], s0);
            atomicAdd(&sstat[c + 1], s1);
            atomicAdd(&sstat[128 + c], q0);
            atomicAdd(&sstat[128 + c + 1], q1);
        }
    }
    __syncthreads();
    if (tid < 256) atomicAdd(&stats[rel * 256 + tid], sstat[tid]);
}

// ---------------- BN finalize (re-zeroes stats for next layer) ----------------
__global__ void k_finalize9(const float* __restrict__ gammaL, const float* __restrict__ betaL) {
    int r = blockIdx.x;
    int c = threadIdx.x;
    float n = (float)c_ndst[r];
    float mu = g_stats[r * 256 + c] / n;
    float var = g_stats[r * 256 + 128 + c] / n - mu * mu;
    float inv = rsqrtf(var + BN_EPS);
    float sc = inv * gammaL[r * D + c];
    g_scale[r * D + c] = sc;
    g_shift[r * D + c] = betaL[r * D + c] - mu * sc;
    g_stats[r * 256 + c] = 0.f;
    g_stats[r * 256 + 128 + c] = 0.f;
}

// ------- fused normalize + 3-rel sum; layer0 -> fp16 feat, layer1 -> fp32 out ---
__global__ void k_fuse_all(const __half* __restrict__ gout,
                           const float4* __restrict__ ra, const float4* __restrict__ rb,
                           const float4* __restrict__ rg, int layer,
                           float4* __restrict__ outF, __half* __restrict__ outH) {
    int i = blockIdx.x * blockDim.x + threadIdx.x;
    if (i >= NTOT * 32) return;
    int row = i >> 5;
    int c4 = i & 31;
    int c = c4 * 4;
    int type = (row < NA) ? 0 : (row < NA + NB) ? 1 : 2;
    int local = row - c_toff[type];
    int r0 = c_rl[type * 3], r1 = c_rl[type * 3 + 1], r2 = c_rl[type * 3 + 2];

    uint2 ha = *(const uint2*)(gout + (size_t)(c_doff[r0] + local) * D + c);
    uint2 hb = *(const uint2*)(gout + (size_t)(c_doff[r1] + local) * D + c);
    uint2 hg = *(const uint2*)(gout + (size_t)(c_doff[r2] + local) * D + c);
    float2 a01 = __half22float2(*(__half2*)&ha.x), a23 = __half22float2(*(__half2*)&ha.y);
    float2 b01 = __half22float2(*(__half2*)&hb.x), b23 = __half22float2(*(__half2*)&hb.y);
    float2 g01 = __half22float2(*(__half2*)&hg.x), g23 = __half22float2(*(__half2*)&hg.y);

    float4 o;
    o.x = a01.x * g_scale[r0 * D + c + 0] + b01.x * g_scale[r1 * D + c + 0] + g01.x * g_scale[r2 * D + c + 0]
        + g_shift[r0 * D + c + 0] + g_shift[r1 * D + c + 0] + g_shift[r2 * D + c + 0];
    o.y = a01.y * g_scale[r0 * D + c + 1] + b01.y * g_scale[r1 * D + c + 1] + g01.y * g_scale[r2 * D + c + 1]
        + g_shift[r0 * D + c + 1] + g_shift[r1 * D + c + 1] + g_shift[r2 * D + c + 1];
    o.z = a23.x * g_scale[r0 * D + c + 2] + b23.x * g_scale[r1 * D + c + 2] + g23.x * g_scale[r2 * D + c + 2]
        + g_shift[r0 * D + c + 2] + g_shift[r1 * D + c + 2] + g_shift[r2 * D + c + 2];
    o.w = a23.y * g_scale[r0 * D + c + 3] + b23.y * g_scale[r1 * D + c + 3] + g23.y * g_scale[r2 * D + c + 3]
        + g_shift[r0 * D + c + 3] + g_shift[r1 * D + c + 3] + g_shift[r2 * D + c + 3];
    if (layer == 1) {
        const float4* rp = (type == 0) ? ra : (type == 1) ? rb : rg;
        float4 rr = rp[(size_t)local * 32 + c4];
        o.x += rr.x; o.y += rr.y; o.z += rr.z; o.w += rr.w;
        outF[i] = o;
    } else {
        ((__half2*)outH)[i * 2] = __floats2half2_rn(o.x, o.y);
        ((__half2*)outH)[i * 2 + 1] = __floats2half2_rn(o.z, o.w);
    }
}

// ---------------- cleanup ----------------
__global__ void k_cleanup() {
    int i = blockIdx.x * blockDim.x + threadIdx.x;
    int n4 = DEG_TOT / 4;
    if (i < n4) {
        ((int4*)g_odeg)[i] = make_int4(0, 0, 0, 0);
        ((int4*)g_ideg)[i] = make_int4(0, 0, 0, 0);
    }
}

// ---------------- host orchestration ----------------
static inline int cdiv(int a, int b) { return (a + b - 1) / b; }

extern "C" void kernel_launch(void* const* d_in, const int* in_sizes, int n_in,
                              void* d_out, int out_size) {
    const float* fa = (const float*)d_in[0];
    const float* fb = (const float*)d_in[1];
    const float* fg = (const float*)d_in[2];
    const float* W = (const float*)d_in[3];
    const float* gamma = (const float*)d_in[5];
    const float* beta = (const float*)d_in[6];

    EdgePtrs E;
    for (int r = 0; r < 9; r++) {
        E.s[r] = (const int*)d_in[7 + 2 * r];
        E.d[r] = (const int*)d_in[8 + 2 * r];
    }

    float* p_stats;
    __half *p_wh, *p_fh, *p_gout;
    cudaGetSymbolAddress((void**)&p_gout, g_gout);
    cudaGetSymbolAddress((void**)&p_stats, g_stats);
    cudaGetSymbolAddress((void**)&p_wh, g_wh);
    cudaGetSymbolAddress((void**)&p_fh, g_fh);

    cudaFuncSetAttribute(k_gemm_fused, cudaFuncAttributeMaxDynamicSharedMemorySize, SMEM_DYN);

    const int TB = 256;

    // 0: W->fp16 + degree count + feat->fp16
    k_prep<<<18 + EBLK + CBLK, TB>>>(E, W, (const float4*)fa, (const float4*)fb,
                                     (const float4*)fg);
    // 1: scan + ns/nd + rowinfo.deg
    k_scan1<<<SCAN_NB, 1024>>>();
    // 2: CSR fill (rowinfo.off)
    k_fill_all<<<cdiv(NE_TOT, TB), TB>>>(E);
    // 3: fused gather+GEMM L0 (ncu target)
    k_gemm_fused<<<NTILES, 512, SMEM_DYN>>>(p_fh, p_wh, 0, p_gout, p_stats);
    // 4: finalize L0
    k_finalize9<<<9, 128>>>(gamma, beta);
    // 5: fuse L0 -> fp16 feat
    k_fuse_all<<<cdiv(NTOT * 32, TB), TB>>>(p_gout, (const float4*)fa, (const float4*)fb,
                                            (const float4*)fg, 0, nullptr, p_fh);
    // 6-8: layer 1
    k_gemm_fused<<<NTILES, 512, SMEM_DYN>>>(p_fh, p_wh, 1, p_gout, p_stats);
    k_finalize9<<<9, 128>>>(gamma + 9 * D, beta + 9 * D);
    k_fuse_all<<<cdiv(NTOT * 32, TB), TB>>>(p_gout, (const float4*)fa, (const float4*)fb,
                                            (const float4*)fg, 1, (float4*)d_out, nullptr);
    // 9: cleanup
    k_cleanup<<<cdiv(DEG_TOT / 4, TB), TB>>>();
}

// round 17
// speedup vs baseline: 1.4363x; 1.0843x over previous
#include <cuda_runtime.h>
#include <cuda_fp16.h>
#include <cstdint>

#define D 128
#define NA 100000
#define NB 150000
#define NG 2000
#define NTOT (NA + NB + NG)      // 252000
#define DEG_TOT 756000
#define NE_TOT 1352000
#define NTILES 5910
#define BN_EPS 1e-5f
#define SCAN_NB ((DEG_TOT + 1023) / 1024)   // 739

#define EBLK ((NE_TOT + 255) / 256)          // 5282
#define CBLK ((NTOT * 32 + 255) / 256)       // 31500

// ---------------- constant boundary tables ----------------
__constant__ int c_doff[10] = {0,150000,250000,252000,352000,354000,504000,604000,754000,756000};
__constant__ int c_soff[10] = {0,100000,250000,350000,352000,502000,504000,604000,754000,756000};
__constant__ int c_eoff[10] = {0,300000,600000,700000,800000,950000,1100000,1200000,1350000,1352000};
__constant__ int c_tbase[10] = {0,1172,1954,1970,2752,2768,3940,4722,5894,5910};
__constant__ int c_stoff[9] = {0, NA, 0, NA + NB, NA, NA + NB, 0, NA, NA + NB};
__constant__ int c_ndst[9] = {NB, NA, NG, NA, NG, NB, NA, NB, NG};
__constant__ int c_rl[9] = {1, 3, 6, 0, 5, 7, 2, 4, 8};
__constant__ int c_toff[3] = {0, NA, NA + NB};

// ---------------- device scratch ----------------
__device__ int g_odeg[DEG_TOT];
__device__ int g_ideg[DEG_TOT];
__device__ int g_offs[DEG_TOT];
__device__ int2 g_rowinfo[DEG_TOT];               // {csr_off (fill), deg (scan1)}
__device__ int g_cursor[DEG_TOT];
__device__ int g_bsum[SCAN_NB];
__device__ int2 g_epack[NE_TOT];                  // {src_byte_off, ns fp32 bits}
__device__ float g_ns[DEG_TOT];
__device__ float g_nd[DEG_TOT];
__device__ __align__(128) __half g_fh[(size_t)NTOT * D];
__device__ __align__(128) __half g_gout[(size_t)DEG_TOT * D];
__device__ float g_stats[9 * 2 * D];
__device__ float g_scale[9 * D];
__device__ float g_shift[9 * D];
__device__ __align__(128) __half g_wh[18 * D * D];

struct EdgePtrs { const int* s[9]; const int* d[9]; };

// ---------------- helpers ----------------
__device__ __forceinline__ uint32_t sw128(uint32_t o) { return o ^ ((o >> 3) & 0x70); }
__device__ __forceinline__ uint32_t toff128(uint32_t row, uint32_t k) {
    return ((k >> 6) << 14) + sw128(row * 128 + ((k & 63) << 1));
}
__device__ __forceinline__ uint32_t smem_u32(const void* p) {
    uint32_t a;
    asm("{ .reg .u64 t; cvta.to.shared.u64 t, %1; cvt.u32.u64 %0, t; }" : "=r"(a) : "l"(p));
    return a;
}
__device__ __forceinline__ void ldsm4(uint32_t& r0, uint32_t& r1, uint32_t& r2, uint32_t& r3,
                                      uint32_t addr) {
    asm volatile("ldmatrix.sync.aligned.m8n8.x4.shared.b16 {%0,%1,%2,%3}, [%4];"
                 : "=r"(r0), "=r"(r1), "=r"(r2), "=r"(r3) : "r"(addr));
}
__device__ __forceinline__ void mma_f16(float* d, const uint32_t* a, uint32_t b0, uint32_t b1) {
    asm volatile(
        "mma.sync.aligned.m16n8k16.row.col.f32.f16.f16.f32 "
        "{%0,%1,%2,%3}, {%4,%5,%6,%7}, {%8,%9}, {%0,%1,%2,%3};"
        : "+f"(d[0]), "+f"(d[1]), "+f"(d[2]), "+f"(d[3])
        : "r"(a[0]), "r"(a[1]), "r"(a[2]), "r"(a[3]), "r"(b0), "r"(b1));
}
__device__ __forceinline__ void cpasync16(uint32_t dst, const void* src) {
    asm volatile("cp.async.ca.shared.global [%0], [%1], 16;" :: "r"(dst), "l"(src));
}
__device__ __forceinline__ void acc8(float* acc, const uint4& v, float w) {
    float2 t0 = __half22float2(*(__half2*)&v.x);
    float2 t1 = __half22float2(*(__half2*)&v.y);
    float2 t2 = __half22float2(*(__half2*)&v.z);
    float2 t3 = __half22float2(*(__half2*)&v.w);
    acc[0] += t0.x * w; acc[1] += t0.y * w;
    acc[2] += t1.x * w; acc[3] += t1.y * w;
    acc[4] += t2.x * w; acc[5] += t2.y * w;
    acc[6] += t3.x * w; acc[7] += t3.y * w;
}

// ---------------- branch A0: degree count ----------------
__global__ void k_count_all(EdgePtrs E) {
    int e = blockIdx.x * blockDim.x + threadIdx.x;
    if (e >= NE_TOT) return;
    int rel = 0;
#pragma unroll
    for (int r = 1; r < 9; r++) if (e >= c_eoff[r]) rel = r;
    int le = e - c_eoff[rel];
    atomicAdd(&g_odeg[c_soff[rel] + E.s[rel][le]], 1);
    atomicAdd(&g_ideg[c_doff[rel] + E.d[rel][le]], 1);
}

// ---------------- branch B: W->fp16 swizzled + feat->fp16 ----------------
__global__ void k_conv(const float* __restrict__ W,
                       const float4* __restrict__ fa4, const float4* __restrict__ fb4,
                       const float4* __restrict__ fg4) {
    if (blockIdx.x < 18) {
        int rel = blockIdx.x;
        const float* w = W + (size_t)rel * D * D;
        char* wh = (char*)g_wh + (size_t)rel * D * D * 2;
        for (int idx = threadIdx.x; idx < D * D; idx += blockDim.x) {
            int k = idx >> 7, n = idx & 127;
            *(__half*)(wh + toff128(n, k)) = __float2half_rn(w[idx]);
        }
        return;
    }
    int i = (blockIdx.x - 18) * blockDim.x + threadIdx.x;
    if (i >= NTOT * 32) return;
    int t = (i < NA * 32) ? 0 : (i < (NA + NB) * 32) ? 1 : 2;
    const float4* src = (t == 0) ? fa4 : (t == 1) ? fb4 : fg4;
    int base4 = (t == 0) ? 0 : (t == 1) ? NA * 32 : (NA + NB) * 32;
    float4 v = src[i - base4];
    ((__half2*)g_fh)[i * 2] = __floats2half2_rn(v.x, v.y);
    ((__half2*)g_fh)[i * 2 + 1] = __floats2half2_rn(v.z, v.w);
}

// ---------------- A1: scan + ns/nd + rowinfo.deg + cursor/stats zero -----------
__global__ void k_scan1() {
    int tid = threadIdx.x;
    int gid = blockIdx.x * 1024 + tid;
    int lane = tid & 31;
    int w = tid >> 5;
    int v = (gid < DEG_TOT) ? g_ideg[gid] : 0;
    if (gid < DEG_TOT) {
        int od = g_odeg[gid];
        g_ns[gid] = (od > 0) ? rsqrtf((float)od) : 0.f;
        g_nd[gid] = (v > 0) ? rsqrtf((float)v) : 0.f;
        g_cursor[gid] = 0;
        g_rowinfo[gid].y = v;
    }
    if (blockIdx.x == 0) {
        for (int i = tid; i < 9 * 256; i += 1024) g_stats[i] = 0.f;
    }
    int inc = v;
#pragma unroll
    for (int s = 1; s < 32; s <<= 1) {
        int x = __shfl_up_sync(0xffffffffu, inc, s);
        if (lane >= s) inc += x;
    }
    __shared__ int wsum[32];
    if (lane == 31) wsum[w] = inc;
    __syncthreads();
    if (w == 0) {
        int x = (lane < 32) ? wsum[lane] : 0;
        int sc = x;
#pragma unroll
        for (int s = 1; s < 32; s <<= 1) {
            int y = __shfl_up_sync(0xffffffffu, sc, s);
            if (lane >= s) sc += y;
        }
        wsum[lane] = sc - x;
    }
    __syncthreads();
    int excl = inc - v + wsum[w];
    if (gid < DEG_TOT) g_offs[gid] = excl;
    if (tid == 1023) g_bsum[blockIdx.x] = excl + v;
}

// ---------------- A2: CSR fill (writes rowinfo.off) ----------------
__global__ __launch_bounds__(256)
void k_fill_all(EdgePtrs E) {
    __shared__ int sb[768];
    __shared__ int wsum[8];
    int t = threadIdx.x;
    int base = t * 3;
    int a0 = (base < SCAN_NB) ? g_bsum[base] : 0;
    int a1 = (base + 1 < SCAN_NB) ? g_bsum[base + 1] : 0;
    int a2 = (base + 2 < SCAN_NB) ? g_bsum[base + 2] : 0;
    int tsum = a0 + a1 + a2;
    int lane = t & 31;
    int inc = tsum;
#pragma unroll
    for (int s = 1; s < 32; s <<= 1) {
        int x = __shfl_up_sync(0xffffffffu, inc, s);
        if (lane >= s) inc += x;
    }
    if (lane == 31) wsum[t >> 5] = inc;
    __syncthreads();
    if (t < 8) {
        int x = wsum[t];
        int sc = x;
#pragma unroll
        for (int s = 1; s < 8; s <<= 1) {
            int y = __shfl_up_sync(0xffu, sc, s);
            if (t >= s) sc += y;
        }
        wsum[t] = sc - x;
    }
    __syncthreads();
    int excl = inc - tsum + wsum[t >> 5];
    sb[base] = excl;
    sb[base + 1] = excl + a0;
    sb[base + 2] = excl + a0 + a1;
    __syncthreads();

    int e = blockIdx.x * blockDim.x + t;
    if (e >= NE_TOT) return;
    int rel = 0;
#pragma unroll
    for (int r = 1; r < 9; r++) if (e >= c_eoff[r]) rel = r;
    int le = e - c_eoff[rel];
    int ss = E.s[rel][le];
    int dd = E.d[rel][le];
    int gslot = c_doff[rel] + dd;
    int ofin = g_offs[gslot] + sb[gslot >> 10];
    int pos = ofin + atomicAdd(&g_cursor[gslot], 1);
    g_epack[pos] = make_int2(ss * 256, __float_as_int(g_ns[c_soff[rel] + ss]));
    g_rowinfo[gslot].x = ofin;
}

// ------- fused gather + GEMM (512 thr, 32x32 warp tiles) + stats ---------------
#define OFF_A    0
#define OFF_B    32768
#define OFF_STAT 65536
#define SMEM_DYN (65536 + 1024 + 1024)

__global__ __launch_bounds__(512, 2)
void k_gemm_fused(const __half* __restrict__ fh, const __half* __restrict__ whAll,
                  int layer, __half* __restrict__ out, float* __restrict__ stats) {
    extern __shared__ char smem_raw[];
    char* smem = (char*)((((uintptr_t)smem_raw) + 1023) & ~(uintptr_t)1023);
    uint32_t sa = smem_u32(smem);
    int tid = threadIdx.x;
    int lane = tid & 31;
    int wid = tid >> 5;        // 0..15
    int bid = blockIdx.x;

    int rel = 0;
#pragma unroll
    for (int r = 1; r < 9; r++) if (bid >= c_tbase[r]) rel = r;
    int rowBase = (bid - c_tbase[rel]) * 128;
    int ndst = c_doff[rel + 1] - c_doff[rel];
    int goutBase = c_doff[rel];

    // prefetch B while gathering A
    {
        const char* sB = (const char*)whAll + (size_t)(layer * 9 + rel) * 32768;
#pragma unroll
        for (int i = tid; i < 2048; i += 512) cpasync16(sa + OFF_B + i * 16, sB + i * 16);
        asm volatile("cp.async.commit_group;" ::: "memory");
    }
    if (tid < 256) ((float*)(smem + OFF_STAT))[tid] = 0.f;

    // ---- gather phase: quarter-warp per row, 64 rows/iter, 2 iters ----
    {
        int l8 = lane & 7;
        const char* fbase = (const char*)fh + (size_t)c_stoff[rel] * 256 + l8 * 32;
        char* atile = smem + OFF_A;
        uint32_t half_tile = (uint32_t)(l8 >> 2) << 14;
        uint32_t colb = (l8 & 3) * 32;
#pragma unroll 1
        for (int it = 0; it < 2; it++) {
            int lrow = it * 64 + wid * 4 + (lane >> 3);
            int grow = rowBase + lrow;
            float acc[16];
#pragma unroll
            for (int j = 0; j < 16; j++) acc[j] = 0.f;
            if (grow < ndst) {
                int gslot = goutBase + grow;
                int2 ri = __ldg(&g_rowinfo[gslot]);
                int dg = ri.y;
                if (dg > 0) {
                    const int2* ep = g_epack + ri.x;
                    int e = 0;
                    for (; e + 2 <= dg; e += 2) {
                        int2 p0 = __ldg(ep + e);
                        int2 p1 = __ldg(ep + e + 1);
                        uint4 v0a = __ldg((const uint4*)(fbase + (uint32_t)p0.x));
                        uint4 v0b = __ldg((const uint4*)(fbase + (uint32_t)p0.x + 16));
                        uint4 v1a = __ldg((const uint4*)(fbase + (uint32_t)p1.x));
                        uint4 v1b = __ldg((const uint4*)(fbase + (uint32_t)p1.x + 16));
                        float w0 = __int_as_float(p0.y), w1 = __int_as_float(p1.y);
                        acc8(acc, v0a, w0);
                        acc8(acc + 8, v0b, w0);
                        acc8(acc, v1a, w1);
                        acc8(acc + 8, v1b, w1);
                    }
                    if (e < dg) {
                        int2 p0 = __ldg(ep + e);
                        uint4 v0a = __ldg((const uint4*)(fbase + (uint32_t)p0.x));
                        uint4 v0b = __ldg((const uint4*)(fbase + (uint32_t)p0.x + 16));
                        float w0 = __int_as_float(p0.y);
                        acc8(acc, v0a, w0);
                        acc8(acc + 8, v0b, w0);
                    }
                    float ndv = __ldg(g_nd + gslot);
#pragma unroll
                    for (int j = 0; j < 16; j++) acc[j] *= ndv;
                }
            }
            uint4 pk0, pk1;
            *(__half2*)&pk0.x = __floats2half2_rn(acc[0], acc[1]);
            *(__half2*)&pk0.y = __floats2half2_rn(acc[2], acc[3]);
            *(__half2*)&pk0.z = __floats2half2_rn(acc[4], acc[5]);
            *(__half2*)&pk0.w = __floats2half2_rn(acc[6], acc[7]);
            *(__half2*)&pk1.x = __floats2half2_rn(acc[8], acc[9]);
            *(__half2*)&pk1.y = __floats2half2_rn(acc[10], acc[11]);
            *(__half2*)&pk1.z = __floats2half2_rn(acc[12], acc[13]);
            *(__half2*)&pk1.w = __floats2half2_rn(acc[14], acc[15]);
            uint32_t rb = (uint32_t)lrow * 128 + colb;
            *(uint4*)(atile + half_tile + sw128(rb)) = pk0;
            *(uint4*)(atile + half_tile + sw128(rb + 16)) = pk1;
        }
    }

    asm volatile("cp.async.wait_group 0;" ::: "memory");
    __syncthreads();

    // ---- GEMM mainloop: warp tile 32 rows x 32 cols (4M x 4N warps) ----
    int m0 = (wid & 3) * 32;
    int n0 = (wid >> 2) * 32;

    float acc[2][4][4];
#pragma unroll
    for (int ai = 0; ai < 2; ai++)
#pragma unroll
        for (int nj = 0; nj < 4; nj++)
#pragma unroll
            for (int j = 0; j < 4; j++) acc[ai][nj][j] = 0.f;

    uint32_t rowAl = lane & 15;
    uint32_t kA = (lane >> 4) << 3;
    uint32_t rowB = (lane & 7) + ((lane >> 4) << 3);
    uint32_t kB = ((lane >> 3) & 1) << 3;

    uint32_t ab = sa + OFF_A;
    uint32_t bb = sa + OFF_B;
#pragma unroll
    for (int k0 = 0; k0 < 128; k0 += 16) {
        uint32_t a0[4], a1[4];
        ldsm4(a0[0], a0[1], a0[2], a0[3], ab + toff128(m0 + rowAl, k0 + kA));
        ldsm4(a1[0], a1[1], a1[2], a1[3], ab + toff128(m0 + 16 + rowAl, k0 + kA));
#pragma unroll
        for (int nb = 0; nb < 2; nb++) {
            uint32_t b0, b1, b2, b3;
            ldsm4(b0, b1, b2, b3, bb + toff128(n0 + nb * 16 + rowB, k0 + kB));
            mma_f16(acc[0][2 * nb], a0, b0, b1);
            mma_f16(acc[0][2 * nb + 1], a0, b2, b3);
            mma_f16(acc[1][2 * nb], a1, b0, b1);
            mma_f16(acc[1][2 * nb + 1], a1, b2, b3);
        }
    }

    // ---- epilogue: gout (fp16) + column stats ----
    int quad = lane >> 2;
    int cp = (lane & 3) * 2;
    float* sstat = (float*)(smem + OFF_STAT);

#pragma unroll
    for (int nj = 0; nj < 4; nj++) {
        int c = n0 + nj * 8 + cp;
        float s0 = 0.f, s1 = 0.f, q0 = 0.f, q1 = 0.f;
#pragma unroll
        for (int ai = 0; ai < 2; ai++) {
            int lr0 = rowBase + m0 + ai * 16 + quad;
            int lr1 = lr0 + 8;
            bool v0 = lr0 < ndst, v1 = lr1 < ndst;
            float x0 = acc[ai][nj][0], x1 = acc[ai][nj][1];
            float y0 = acc[ai][nj][2], y1 = acc[ai][nj][3];
            if (v0) *(__half2*)(out + (size_t)(goutBase + lr0) * D + c) = __floats2half2_rn(x0, x1);
            if (v1) *(__half2*)(out + (size_t)(goutBase + lr1) * D + c) = __floats2half2_rn(y0, y1);
            s0 += (v0 ? x0 : 0.f) + (v1 ? y0 : 0.f);
            s1 += (v0 ? x1 : 0.f) + (v1 ? y1 : 0.f);
            q0 += (v0 ? x0 * x0 : 0.f) + (v1 ? y0 * y0 : 0.f);
            q1 += (v0 ? x1 * x1 : 0.f) + (v1 ? y1 * y1 : 0.f);
        }
#pragma unroll
        for (int S = 4; S <= 16; S <<= 1) {
            s0 += __shfl_xor_sync(0xffffffffu, s0, S);
            s1 += __shfl_xor_sync(0xffffffffu, s1, S);
            q0 += __shfl_xor_sync(0xffffffffu, q0, S);
            q1 += __shfl_xor_sync(0xffffffffu, q1, S);
        }
        if (lane < 4) {
            atomicAdd(&sstat[c], s0);
            atomicAdd(&sstat[c + 1], s1);
            atomicAdd(&sstat[128 + c], q0);
            atomicAdd(&sstat[128 + c + 1], q1);
        }
    }
    __syncthreads();
    if (tid < 256) atomicAdd(&stats[rel * 256 + tid], sstat[tid]);
}

// ---------------- BN finalize (re-zeroes stats for next layer) ----------------
__global__ void k_finalize9(const float* __restrict__ gammaL, const float* __restrict__ betaL) {
    int r = blockIdx.x;
    int c = threadIdx.x;
    float n = (float)c_ndst[r];
    float mu = g_stats[r * 256 + c] / n;
    float var = g_stats[r * 256 + 128 + c] / n - mu * mu;
    float inv = rsqrtf(var + BN_EPS);
    float sc = inv * gammaL[r * D + c];
    g_scale[r * D + c] = sc;
    g_shift[r * D + c] = betaL[r * D + c] - mu * sc;
    g_stats[r * 256 + c] = 0.f;
    g_stats[r * 256 + 128 + c] = 0.f;
}

// ------- fused normalize + 3-rel sum (uint4 granularity) -----------------------
__global__ void k_fuse_all(const __half* __restrict__ gout,
                           const float4* __restrict__ ra, const float4* __restrict__ rb,
                           const float4* __restrict__ rg, int layer,
                           float4* __restrict__ outF, __half* __restrict__ outH) {
    int i = blockIdx.x * blockDim.x + threadIdx.x;
    if (i >= NTOT * 16) return;
    int row = i >> 4;
    int c = (i & 15) * 8;
    int type = (row < NA) ? 0 : (row < NA + NB) ? 1 : 2;
    int local = row - c_toff[type];
    int r0 = c_rl[type * 3], r1 = c_rl[type * 3 + 1], r2 = c_rl[type * 3 + 2];

    uint4 ha = *(const uint4*)(gout + (size_t)(c_doff[r0] + local) * D + c);
    uint4 hb = *(const uint4*)(gout + (size_t)(c_doff[r1] + local) * D + c);
    uint4 hg = *(const uint4*)(gout + (size_t)(c_doff[r2] + local) * D + c);
    float av[8], bv[8], gv[8];
    {
        const uint32_t* pa = &ha.x;
        const uint32_t* pb = &hb.x;
        const uint32_t* pg = &hg.x;
#pragma unroll
        for (int j = 0; j < 4; j++) {
            float2 t;
            t = __half22float2(*(__half2*)&pa[j]); av[2 * j] = t.x; av[2 * j + 1] = t.y;
            t = __half22float2(*(__half2*)&pb[j]); bv[2 * j] = t.x; bv[2 * j + 1] = t.y;
            t = __half22float2(*(__half2*)&pg[j]); gv[2 * j] = t.x; gv[2 * j + 1] = t.y;
        }
    }
    float sc0[8], sc1[8], sc2[8], sh[8];
    {
        float4 t0 = *(const float4*)(g_scale + r0 * D + c);
        float4 t1 = *(const float4*)(g_scale + r0 * D + c + 4);
        sc0[0]=t0.x; sc0[1]=t0.y; sc0[2]=t0.z; sc0[3]=t0.w;
        sc0[4]=t1.x; sc0[5]=t1.y; sc0[6]=t1.z; sc0[7]=t1.w;
        t0 = *(const float4*)(g_scale + r1 * D + c);
        t1 = *(const float4*)(g_scale + r1 * D + c + 4);
        sc1[0]=t0.x; sc1[1]=t0.y; sc1[2]=t0.z; sc1[3]=t0.w;
        sc1[4]=t1.x; sc1[5]=t1.y; sc1[6]=t1.z; sc1[7]=t1.w;
        t0 = *(const float4*)(g_scale + r2 * D + c);
        t1 = *(const float4*)(g_scale + r2 * D + c + 4);
        sc2[0]=t0.x; sc2[1]=t0.y; sc2[2]=t0.z; sc2[3]=t0.w;
        sc2[4]=t1.x; sc2[5]=t1.y; sc2[6]=t1.z; sc2[7]=t1.w;
        float4 u0 = *(const float4*)(g_shift + r0 * D + c);
        float4 u1 = *(const float4*)(g_shift + r0 * D + c + 4);
        float4 v0 = *(const float4*)(g_shift + r1 * D + c);
        float4 v1 = *(const float4*)(g_shift + r1 * D + c + 4);
        float4 w0 = *(const float4*)(g_shift + r2 * D + c);
        float4 w1 = *(const float4*)(g_shift + r2 * D + c + 4);
        sh[0]=u0.x+v0.x+w0.x; sh[1]=u0.y+v0.y+w0.y; sh[2]=u0.z+v0.z+w0.z; sh[3]=u0.w+v0.w+w0.w;
        sh[4]=u1.x+v1.x+w1.x; sh[5]=u1.y+v1.y+w1.y; sh[6]=u1.z+v1.z+w1.z; sh[7]=u1.w+v1.w+w1.w;
    }
    float o[8];
#pragma unroll
    for (int j = 0; j < 8; j++)
        o[j] = av[j] * sc0[j] + bv[j] * sc1[j] + gv[j] * sc2[j] + sh[j];

    if (layer == 1) {
        const float4* rp = (type == 0) ? ra : (type == 1) ? rb : rg;
        float4 rr0 = rp[(size_t)local * 32 + (i & 15) * 2];
        float4 rr1 = rp[(size_t)local * 32 + (i & 15) * 2 + 1];
        o[0] += rr0.x; o[1] += rr0.y; o[2] += rr0.z; o[3] += rr0.w;
        o[4] += rr1.x; o[5] += rr1.y; o[6] += rr1.z; o[7] += rr1.w;
        outF[(size_t)i * 2] = make_float4(o[0], o[1], o[2], o[3]);
        outF[(size_t)i * 2 + 1] = make_float4(o[4], o[5], o[6], o[7]);
    } else {
        uint4 pk;
        *(__half2*)&pk.x = __floats2half2_rn(o[0], o[1]);
        *(__half2*)&pk.y = __floats2half2_rn(o[2], o[3]);
        *(__half2*)&pk.z = __floats2half2_rn(o[4], o[5]);
        *(__half2*)&pk.w = __floats2half2_rn(o[6], o[7]);
        *(uint4*)(outH + (size_t)i * 8) = pk;
    }
}

// ---------------- cleanup (side branch) ----------------
__global__ void k_cleanup() {
    int i = blockIdx.x * blockDim.x + threadIdx.x;
    int n4 = DEG_TOT / 4;
    if (i < n4) {
        ((int4*)g_odeg)[i] = make_int4(0, 0, 0, 0);
        ((int4*)g_ideg)[i] = make_int4(0, 0, 0, 0);
    }
}

// ---------------- host orchestration ----------------
static inline int cdiv(int a, int b) { return (a + b - 1) / b; }

extern "C" void kernel_launch(void* const* d_in, const int* in_sizes, int n_in,
                              void* d_out, int out_size) {
    const float* fa = (const float*)d_in[0];
    const float* fb = (const float*)d_in[1];
    const float* fg = (const float*)d_in[2];
    const float* W = (const float*)d_in[3];
    const float* gamma = (const float*)d_in[5];
    const float* beta = (const float*)d_in[6];

    EdgePtrs E;
    for (int r = 0; r < 9; r++) {
        E.s[r] = (const int*)d_in[7 + 2 * r];
        E.d[r] = (const int*)d_in[8 + 2 * r];
    }

    float* p_stats;
    __half *p_wh, *p_fh, *p_gout;
    cudaGetSymbolAddress((void**)&p_gout, g_gout);
    cudaGetSymbolAddress((void**)&p_stats, g_stats);
    cudaGetSymbolAddress((void**)&p_wh, g_wh);
    cudaGetSymbolAddress((void**)&p_fh, g_fh);

    cudaFuncSetAttribute(k_gemm_fused, cudaFuncAttributeMaxDynamicSharedMemorySize, SMEM_DYN);

    const int TB = 256;

    // side stream + events for forked capture (host objects; never freed mid-capture)
    cudaStream_t s2;
    cudaStreamCreateWithFlags(&s2, cudaStreamNonBlocking);
    cudaEvent_t eFork, eConv, eScan, eDone;
    cudaEventCreateWithFlags(&eFork, cudaEventDisableTiming);
    cudaEventCreateWithFlags(&eConv, cudaEventDisableTiming);
    cudaEventCreateWithFlags(&eScan, cudaEventDisableTiming);
    cudaEventCreateWithFlags(&eDone, cudaEventDisableTiming);

    // fork: branch B (conv) runs concurrent with branch A (count->scan->fill)
    cudaEventRecord(eFork, 0);
    cudaStreamWaitEvent(s2, eFork, 0);
    k_conv<<<18 + CBLK, TB, 0, s2>>>(W, (const float4*)fa, (const float4*)fb,
                                     (const float4*)fg);
    cudaEventRecord(eConv, s2);

    k_count_all<<<EBLK, TB>>>(E);
    k_scan1<<<SCAN_NB, 1024>>>();
    cudaEventRecord(eScan, 0);
    k_fill_all<<<cdiv(NE_TOT, TB), TB>>>(E);

    // cleanup on side branch (needs scan1 done; off critical path)
    cudaStreamWaitEvent(s2, eScan, 0);
    k_cleanup<<<cdiv(DEG_TOT / 4, TB), TB, 0, s2>>>();
    cudaEventRecord(eDone, s2);

    // join conv before GEMM L0
    cudaStreamWaitEvent(0, eConv, 0);

    // layer 0
    k_gemm_fused<<<NTILES, 512, SMEM_DYN>>>(p_fh, p_wh, 0, p_gout, p_stats);
    k_finalize9<<<9, 128>>>(gamma, beta);
    k_fuse_all<<<cdiv(NTOT * 16, TB), TB>>>(p_gout, (const float4*)fa, (const float4*)fb,
                                            (const float4*)fg, 0, nullptr, p_fh);
    // layer 1
    k_gemm_fused<<<NTILES, 512, SMEM_DYN>>>(p_fh, p_wh, 1, p_gout, p_stats);
    k_finalize9<<<9, 128>>>(gamma + 9 * D, beta + 9 * D);
    k_fuse_all<<<cdiv(NTOT * 16, TB), TB>>>(p_gout, (const float4*)fa, (const float4*)fb,
                                            (const float4*)fg, 1, (float4*)d_out, nullptr);

    // rejoin side branch before capture ends
    cudaStreamWaitEvent(0, eDone, 0);
}